// round 1
// baseline (speedup 1.0000x reference)
#include <cuda_runtime.h>
#include <math.h>

// ---------------------------------------------------------------------------
// Problem constants (from reference):
//   B=8, L=1024, d_model=1024, S=1000, d_llm=4096, H=16, E=64, d_inner=1024
// ---------------------------------------------------------------------------
#define BL    8192          // B*L rows
#define DMODEL 1024
#define DLLM  4096
#define DINNER 1024
#define SEQ_S 1000
#define NHEAD 16
#define EDIM  64

// ---------------------------------------------------------------------------
// Scratch (device globals — no allocation allowed)
// ---------------------------------------------------------------------------
__device__ float g_qs[BL * DINNER];
__device__ float g_ql[BL * DINNER];
__device__ float g_ks[SEQ_S * DINNER];
__device__ float g_vs[SEQ_S * DINNER];
__device__ float g_kl[SEQ_S * DINNER];
__device__ float g_vl[SEQ_S * DINNER];
__device__ float g_attn[BL * DINNER];

// ---------------------------------------------------------------------------
// SGEMM with bias: C[M,N] = A[M,K] @ W[K,N] + b[N]
// 128x128 tile, BK=8, 256 threads, 8x8 per thread.
// Requirements: K % 8 == 0, N % 128 == 0 (true for all our GEMMs). M guarded.
// ---------------------------------------------------------------------------
__global__ __launch_bounds__(256)
void sgemm_bias(const float* __restrict__ A, const float* __restrict__ W,
                const float* __restrict__ bias, float* __restrict__ C,
                int M, int N, int K)
{
    const int BM = 128, BN = 128, BK = 8, TM = 8, TN = 8;
    __shared__ float As[BK][BM];
    __shared__ float Bs[BK][BN];

    const int tid = threadIdx.x;
    const int tx = tid & 15;          // 0..15  -> 8 output cols each
    const int ty = tid >> 4;          // 0..15  -> 8 output rows each
    const int rowBase = blockIdx.y * BM;
    const int colBase = blockIdx.x * BN;

    // A tile load mapping: one float4 per thread along K
    const int aRow = tid >> 1;            // 0..127
    const int aK   = (tid & 1) * 4;       // 0 or 4
    // B tile load mapping: one float4 per thread along N
    const int bK   = tid >> 5;            // 0..7
    const int bCol = (tid & 31) * 4;      // 0..124

    float acc[TM][TN];
#pragma unroll
    for (int i = 0; i < TM; i++)
#pragma unroll
        for (int j = 0; j < TN; j++) acc[i][j] = 0.f;

    for (int k0 = 0; k0 < K; k0 += BK) {
        // Load A (guard M)
        float4 av = make_float4(0.f, 0.f, 0.f, 0.f);
        int gRow = rowBase + aRow;
        if (gRow < M)
            av = *reinterpret_cast<const float4*>(A + (size_t)gRow * K + k0 + aK);
        As[aK + 0][aRow] = av.x;
        As[aK + 1][aRow] = av.y;
        As[aK + 2][aRow] = av.z;
        As[aK + 3][aRow] = av.w;
        // Load B (always in bounds)
        float4 bv = *reinterpret_cast<const float4*>(
            W + (size_t)(k0 + bK) * N + colBase + bCol);
        *reinterpret_cast<float4*>(&Bs[bK][bCol]) = bv;
        __syncthreads();

#pragma unroll
        for (int kk = 0; kk < BK; kk++) {
            float rm[TM], rn[TN];
            float4 m0 = *reinterpret_cast<const float4*>(&As[kk][ty * TM]);
            float4 m1 = *reinterpret_cast<const float4*>(&As[kk][ty * TM + 4]);
            rm[0]=m0.x; rm[1]=m0.y; rm[2]=m0.z; rm[3]=m0.w;
            rm[4]=m1.x; rm[5]=m1.y; rm[6]=m1.z; rm[7]=m1.w;
            float4 n0 = *reinterpret_cast<const float4*>(&Bs[kk][tx * TN]);
            float4 n1 = *reinterpret_cast<const float4*>(&Bs[kk][tx * TN + 4]);
            rn[0]=n0.x; rn[1]=n0.y; rn[2]=n0.z; rn[3]=n0.w;
            rn[4]=n1.x; rn[5]=n1.y; rn[6]=n1.z; rn[7]=n1.w;
#pragma unroll
            for (int i = 0; i < TM; i++)
#pragma unroll
                for (int j = 0; j < TN; j++)
                    acc[i][j] += rm[i] * rn[j];
        }
        __syncthreads();
    }

    // Epilogue: += bias, guarded rows, float4 stores
#pragma unroll
    for (int i = 0; i < TM; i++) {
        int r = rowBase + ty * TM + i;
        if (r >= M) continue;
#pragma unroll
        for (int j = 0; j < TN; j += 4) {
            int c = colBase + tx * TN + j;
            float4 o;
            o.x = acc[i][j + 0] + bias[c + 0];
            o.y = acc[i][j + 1] + bias[c + 1];
            o.z = acc[i][j + 2] + bias[c + 2];
            o.w = acc[i][j + 3] + bias[c + 3];
            *reinterpret_cast<float4*>(C + (size_t)r * N + c) = o;
        }
    }
}

// ---------------------------------------------------------------------------
// Fused cross-attention for one of the two streams.
//   Q: [BL, 1024]   (head h at col h*64)
//   K,V: [S, 1024]
//   O: [BL, 1024]; out = softmax(Q Kt / 8) V, scaled by *wptr.
//   accumulate==0 -> O = w*attn ; accumulate==1 -> O += w*attn
// One block: 32 query rows x 1 head, 128 threads.
// Thread t: row r = t/4, col-group g = t%4 (16 output cols), online softmax.
// ---------------------------------------------------------------------------
__global__ __launch_bounds__(128)
void attn32(const float* __restrict__ Q, const float* __restrict__ Kmat,
            const float* __restrict__ Vmat, float* __restrict__ O,
            const float* __restrict__ wptr, int accumulate)
{
    const int h = blockIdx.y;
    const int qBase = blockIdx.x * 32;
    const int t = threadIdx.x;
    const int r = t >> 2;       // 0..31
    const int g = t & 3;        // 0..3
    const int c0 = g * 16;

    __shared__ float q_sm[32][68];
    __shared__ float kv_sm[64][68];
    __shared__ float p_sm[32][68];

    // --- load Q tile (32x64), float4, fully in-bounds ---
#pragma unroll
    for (int i = 0; i < 4; i++) {
        int f = i * 128 + t;              // float4 index, 512 total
        int row = f >> 4;                 // 16 float4 per row
        int e4 = (f & 15) * 4;
        float4 v4 = *reinterpret_cast<const float4*>(
            Q + (size_t)(qBase + row) * DINNER + h * EDIM + e4);
        *reinterpret_cast<float4*>(&q_sm[row][e4]) = v4;
    }

    float acc[16];
#pragma unroll
    for (int j = 0; j < 16; j++) acc[j] = 0.f;
    float m_run = -INFINITY;
    float lsum = 0.f;

    const float scale = 0.125f;   // 1/sqrt(64)

    for (int s0 = 0; s0 < SEQ_S; s0 += 64) {
        __syncthreads();   // prior-iteration V reads done before overwriting kv_sm

        // --- load K chunk (64x64) with zero-fill past S ---
#pragma unroll
        for (int i = 0; i < 8; i++) {
            int f = i * 128 + t;          // 1024 float4
            int srow = f >> 4;
            int e4 = (f & 15) * 4;
            float4 v4 = make_float4(0.f, 0.f, 0.f, 0.f);
            if (s0 + srow < SEQ_S)
                v4 = *reinterpret_cast<const float4*>(
                    Kmat + (size_t)(s0 + srow) * DINNER + h * EDIM + e4);
            *reinterpret_cast<float4*>(&kv_sm[srow][e4]) = v4;
        }
        __syncthreads();

        // --- scores: thread handles s_local = g + 4*i, i=0..15 ---
        float sc[16];
#pragma unroll
        for (int i = 0; i < 16; i++) sc[i] = 0.f;
#pragma unroll
        for (int e0 = 0; e0 < 64; e0 += 4) {
            float4 qv = *reinterpret_cast<const float4*>(&q_sm[r][e0]);
#pragma unroll
            for (int i = 0; i < 16; i++) {
                float4 kv4 = *reinterpret_cast<const float4*>(&kv_sm[g + 4 * i][e0]);
                sc[i] += qv.x * kv4.x + qv.y * kv4.y + qv.z * kv4.z + qv.w * kv4.w;
            }
        }
        float mloc = -INFINITY;
#pragma unroll
        for (int i = 0; i < 16; i++) {
            sc[i] *= scale;
            if (s0 + g + 4 * i >= SEQ_S) sc[i] = -INFINITY;
            mloc = fmaxf(mloc, sc[i]);
        }
        // group (4-lane) max
        mloc = fmaxf(mloc, __shfl_xor_sync(0xffffffffu, mloc, 1));
        mloc = fmaxf(mloc, __shfl_xor_sync(0xffffffffu, mloc, 2));

        float m_new = fmaxf(m_run, mloc);
        float corr = __expf(m_run - m_new);   // 0 on first chunk
        m_run = m_new;
        lsum *= corr;
#pragma unroll
        for (int j = 0; j < 16; j++) acc[j] *= corr;

        float ls = 0.f;
#pragma unroll
        for (int i = 0; i < 16; i++) {
            float p = __expf(sc[i] - m_new);  // -INF -> 0
            ls += p;
            p_sm[r][g + 4 * i] = p;
        }
        ls += __shfl_xor_sync(0xffffffffu, ls, 1);
        ls += __shfl_xor_sync(0xffffffffu, ls, 2);
        lsum += ls;

        __syncthreads();   // p visible; K reads done

        // --- load V chunk into kv_sm ---
#pragma unroll
        for (int i = 0; i < 8; i++) {
            int f = i * 128 + t;
            int srow = f >> 4;
            int e4 = (f & 15) * 4;
            float4 v4 = make_float4(0.f, 0.f, 0.f, 0.f);
            if (s0 + srow < SEQ_S)
                v4 = *reinterpret_cast<const float4*>(
                    Vmat + (size_t)(s0 + srow) * DINNER + h * EDIM + e4);
            *reinterpret_cast<float4*>(&kv_sm[srow][e4]) = v4;
        }
        __syncthreads();

        // --- accumulate P @ V for own 16 columns ---
#pragma unroll 4
        for (int s = 0; s < 64; s++) {
            float p = p_sm[r][s];
            float4 v0 = *reinterpret_cast<const float4*>(&kv_sm[s][c0 + 0]);
            float4 v1 = *reinterpret_cast<const float4*>(&kv_sm[s][c0 + 4]);
            float4 v2 = *reinterpret_cast<const float4*>(&kv_sm[s][c0 + 8]);
            float4 v3 = *reinterpret_cast<const float4*>(&kv_sm[s][c0 + 12]);
            acc[0]  += p * v0.x; acc[1]  += p * v0.y; acc[2]  += p * v0.z; acc[3]  += p * v0.w;
            acc[4]  += p * v1.x; acc[5]  += p * v1.y; acc[6]  += p * v1.z; acc[7]  += p * v1.w;
            acc[8]  += p * v2.x; acc[9]  += p * v2.y; acc[10] += p * v2.z; acc[11] += p * v2.w;
            acc[12] += p * v3.x; acc[13] += p * v3.y; acc[14] += p * v3.z; acc[15] += p * v3.w;
        }
    }

    const float w = *wptr;
    const float inv = w / lsum;
    float* outp = O + (size_t)(qBase + r) * DINNER + h * EDIM + c0;
#pragma unroll
    for (int j = 0; j < 16; j += 4) {
        float4 o;
        o.x = acc[j + 0] * inv;
        o.y = acc[j + 1] * inv;
        o.z = acc[j + 2] * inv;
        o.w = acc[j + 3] * inv;
        if (accumulate) {
            float4 prev = *reinterpret_cast<float4*>(outp + j);
            o.x += prev.x; o.y += prev.y; o.z += prev.z; o.w += prev.w;
        }
        *reinterpret_cast<float4*>(outp + j) = o;
    }
}

// ---------------------------------------------------------------------------
// Launch
// ---------------------------------------------------------------------------
extern "C" void kernel_launch(void* const* d_in, const int* in_sizes, int n_in,
                              void* d_out, int out_size)
{
    const float* target = (const float*)d_in[0];   // [8192,1024]
    const float* source = (const float*)d_in[1];   // [1000,4096]
    const float* value  = (const float*)d_in[2];   // [1000,4096]
    const float* Wq_s = (const float*)d_in[3];  const float* bq_s = (const float*)d_in[4];
    const float* Wk_s = (const float*)d_in[5];  const float* bk_s = (const float*)d_in[6];
    const float* Wv_s = (const float*)d_in[7];  const float* bv_s = (const float*)d_in[8];
    const float* Wq_l = (const float*)d_in[9];  const float* bq_l = (const float*)d_in[10];
    const float* Wk_l = (const float*)d_in[11]; const float* bk_l = (const float*)d_in[12];
    const float* Wv_l = (const float*)d_in[13]; const float* bv_l = (const float*)d_in[14];
    const float* Wo   = (const float*)d_in[15]; const float* bo   = (const float*)d_in[16];
    const float* alpha = (const float*)d_in[17];
    const float* beta  = (const float*)d_in[18];
    float* out = (float*)d_out;

    float *qs, *ql, *ks, *vs, *kl, *vl, *attn;
    cudaGetSymbolAddress((void**)&qs,   g_qs);
    cudaGetSymbolAddress((void**)&ql,   g_ql);
    cudaGetSymbolAddress((void**)&ks,   g_ks);
    cudaGetSymbolAddress((void**)&vs,   g_vs);
    cudaGetSymbolAddress((void**)&kl,   g_kl);
    cudaGetSymbolAddress((void**)&vl,   g_vl);
    cudaGetSymbolAddress((void**)&attn, g_attn);

    // Projections
    {
        dim3 gq(DINNER / 128, BL / 128);           // (8, 64)
        sgemm_bias<<<gq, 256>>>(target, Wq_s, bq_s, qs, BL, DINNER, DMODEL);
        sgemm_bias<<<gq, 256>>>(target, Wq_l, bq_l, ql, BL, DINNER, DMODEL);
        dim3 gkv(DINNER / 128, (SEQ_S + 127) / 128); // (8, 8)
        sgemm_bias<<<gkv, 256>>>(source, Wk_s, bk_s, ks, SEQ_S, DINNER, DLLM);
        sgemm_bias<<<gkv, 256>>>(value,  Wv_s, bv_s, vs, SEQ_S, DINNER, DLLM);
        sgemm_bias<<<gkv, 256>>>(source, Wk_l, bk_l, kl, SEQ_S, DINNER, DLLM);
        sgemm_bias<<<gkv, 256>>>(value,  Wv_l, bv_l, vl, SEQ_S, DINNER, DLLM);
    }

    // Attention (two streams combined into attn buffer)
    {
        dim3 ga(BL / 32, NHEAD);                    // (256, 16)
        attn32<<<ga, 128>>>(qs, ks, vs, attn, alpha, 0);
        attn32<<<ga, 128>>>(ql, kl, vl, attn, beta, 1);
    }

    // Output projection -> d_out
    {
        dim3 go(DLLM / 128, BL / 128);              // (32, 64)
        sgemm_bias<<<go, 256>>>(attn, Wo, bo, out, BL, DLLM, DINNER);
    }
}

// round 3
// speedup vs baseline: 1.6418x; 1.6418x over previous
#include <cuda_runtime.h>
#include <cuda_bf16.h>
#include <math.h>
#include <stdint.h>

// ---------------------------------------------------------------------------
// Problem constants: B=8, L=1024, d_model=1024, S=1000, d_llm=4096, H=16, E=64
// ---------------------------------------------------------------------------
#define BL     8192
#define DMODEL 1024
#define DLLM   4096
#define DINNER 1024
#define SEQ_S  1000
#define NHEAD  16
#define EDIM   64

// ---------------------------------------------------------------------------
// Portable PTX helpers (compile under base compute_103 target — NO tcgen05)
// ---------------------------------------------------------------------------
__device__ __forceinline__ uint32_t smem_u32(const void* p) {
    uint32_t a;
    asm("{ .reg .u64 t; cvta.to.shared.u64 t, %1; cvt.u32.u64 %0, t; }"
        : "=r"(a) : "l"(p));
    return a;
}

#define SWZ(o) ((o) ^ (((o) >> 3) & 0x70))   // Swizzle<3,4,3> on 128B rows

#define CP_ASYNC16(dst, src) \
    asm volatile("cp.async.cg.shared.global [%0], [%1], 16;\n" :: "r"(dst), "l"(src))
#define CP_COMMIT() asm volatile("cp.async.commit_group;\n" ::: "memory")
#define CP_WAIT1()  asm volatile("cp.async.wait_group 1;\n" ::: "memory")
#define STS_ZERO16(addr) \
    asm volatile("st.shared.v4.b32 [%0], {%1,%1,%1,%1};\n" :: "r"(addr), "r"(0u) : "memory")

__device__ __forceinline__ void ldsm4(uint32_t* r, uint32_t a) {
    asm volatile("ldmatrix.sync.aligned.m8n8.x4.shared.b16 {%0,%1,%2,%3}, [%4];\n"
        : "=r"(r[0]), "=r"(r[1]), "=r"(r[2]), "=r"(r[3]) : "r"(a));
}
__device__ __forceinline__ void mma16816(float* c, const uint32_t* a, const uint32_t* b) {
    asm volatile(
        "mma.sync.aligned.m16n8k16.row.col.f32.bf16.bf16.f32 "
        "{%0,%1,%2,%3}, {%4,%5,%6,%7}, {%8,%9}, {%0,%1,%2,%3};\n"
        : "+f"(c[0]), "+f"(c[1]), "+f"(c[2]), "+f"(c[3])
        : "r"(a[0]), "r"(a[1]), "r"(a[2]), "r"(a[3]), "r"(b[0]), "r"(b[1]));
}

// ---------------------------------------------------------------------------
// Scratch (device globals — no allocation allowed)
// ---------------------------------------------------------------------------
__device__ float g_qs[BL * DINNER];
__device__ float g_ql[BL * DINNER];
__device__ float g_ks[SEQ_S * DINNER];
__device__ float g_vs[SEQ_S * DINNER];
__device__ float g_kl[SEQ_S * DINNER];
__device__ float g_vl[SEQ_S * DINNER];
__device__ float g_attn[BL * DINNER];
// bf16 split activations
__device__ __nv_bfloat16 g_th[BL * DMODEL],  g_tl[BL * DMODEL];
__device__ __nv_bfloat16 g_sh[SEQ_S * DLLM], g_sl[SEQ_S * DLLM];
__device__ __nv_bfloat16 g_vh[SEQ_S * DLLM], g_vl2[SEQ_S * DLLM];
__device__ __nv_bfloat16 g_ah[BL * DINNER],  g_al[BL * DINNER];
// bf16 split transposed weights [N, K]
__device__ __nv_bfloat16 g_wqsh[DINNER * DMODEL], g_wqsl[DINNER * DMODEL];
__device__ __nv_bfloat16 g_wqlh[DINNER * DMODEL], g_wqll[DINNER * DMODEL];
__device__ __nv_bfloat16 g_wksh[DINNER * DLLM],   g_wksl[DINNER * DLLM];
__device__ __nv_bfloat16 g_wvsh[DINNER * DLLM],   g_wvsl[DINNER * DLLM];
__device__ __nv_bfloat16 g_wklh[DINNER * DLLM],   g_wkll[DINNER * DLLM];
__device__ __nv_bfloat16 g_wvlh[DINNER * DLLM],   g_wvll[DINNER * DLLM];
__device__ __nv_bfloat16 g_woh[DLLM * DINNER],    g_wol[DLLM * DINNER];

// ---------------------------------------------------------------------------
// Prepass kernels
// ---------------------------------------------------------------------------
__global__ void split_f32(const float* __restrict__ x, __nv_bfloat16* __restrict__ hi,
                          __nv_bfloat16* __restrict__ lo, int n)
{
    int i = blockIdx.x * blockDim.x + threadIdx.x;
    int stride = gridDim.x * blockDim.x;
    for (; i < n; i += stride) {
        float v = x[i];
        __nv_bfloat16 h = __float2bfloat16(v);
        hi[i] = h;
        lo[i] = __float2bfloat16(v - __bfloat162float(h));
    }
}

// W[K,N] fp32 -> Th/Tl[N,K] bf16 split (transposed, K-major)
__global__ void split_transpose(const float* __restrict__ W, __nv_bfloat16* __restrict__ Th,
                                __nv_bfloat16* __restrict__ Tl, int K, int N)
{
    __shared__ float t[32][33];
    int n0 = blockIdx.x * 32, k0 = blockIdx.y * 32;
    int tx = threadIdx.x, ty = threadIdx.y;  // 32 x 8
#pragma unroll
    for (int i = 0; i < 32; i += 8)
        t[ty + i][tx] = W[(size_t)(k0 + ty + i) * N + n0 + tx];
    __syncthreads();
#pragma unroll
    for (int i = 0; i < 32; i += 8) {
        int n = n0 + ty + i;
        float v = t[tx][ty + i];
        __nv_bfloat16 h = __float2bfloat16(v);
        Th[(size_t)n * K + k0 + tx] = h;
        Tl[(size_t)n * K + k0 + tx] = __float2bfloat16(v - __bfloat162float(h));
    }
}

// ---------------------------------------------------------------------------
// HMMA GEMM (bf16 split-2, 3 MMA terms):
//   C[M,N] = (Ah+Al)[M,K] @ (Bh+Bl)[N,K]^T + bias[N]   (Al*Bl dropped)
// Block 128x128, BK=64 (128B SW128 rows), 8 warps (4m x 2n), warp 32x64.
// 2-stage cp.async pipeline. Batched over blockIdx.z.
// Requires N % 128 == 0, K % 64 == 0; M guarded.
// ---------------------------------------------------------------------------
struct Batch {
    const __nv_bfloat16 *Ah[4], *Al[4], *Bh[4], *Bl[4];
    const float* bias[4];
    float* C[4];
};

#define STG      65536          // bytes per pipeline stage (4 x 16KB tiles)
#define T_AH     0
#define T_AL     16384
#define T_BH     32768
#define T_BL     49152
#define GEMM_SMEM (2 * STG)     // 128 KB

__global__ __launch_bounds__(256)
void gemm_hmma(Batch p, int M, int N, int K)
{
    extern __shared__ __align__(1024) char smem[];
    const int z = blockIdx.z;
    const __nv_bfloat16* __restrict__ Ah = p.Ah[z];
    const __nv_bfloat16* __restrict__ Al = p.Al[z];
    const __nv_bfloat16* __restrict__ Bh = p.Bh[z];
    const __nv_bfloat16* __restrict__ Bl = p.Bl[z];

    const int tid = threadIdx.x;
    const int wid = tid >> 5, lid = tid & 31;
    const int wm = wid & 3, wn = wid >> 2;       // warp grid 4(m) x 2(n)
    const int m0 = blockIdx.y * 128, n0 = blockIdx.x * 128;
    const uint32_t sb = smem_u32(smem);

    float c[2][8][4];
#pragma unroll
    for (int i = 0; i < 2; i++)
#pragma unroll
        for (int j = 0; j < 8; j++)
#pragma unroll
            for (int q = 0; q < 4; q++) c[i][j][q] = 0.f;

    const int NC = K >> 6;

    // ---- stage loader: 128 rows x 8 16B-chunks for each of 4 tiles ----
#define LOAD_STAGE(cchunk) do { \
        const uint32_t st_ = sb + ((cchunk) & 1) * STG; \
        const int k0_ = (cchunk) << 6; \
        _Pragma("unroll") \
        for (int i_ = 0; i_ < 4; i_++) { \
            int idx_ = i_ * 256 + tid; \
            int r_ = idx_ >> 3, u_ = idx_ & 7; \
            uint32_t sw_ = SWZ((uint32_t)(r_ * 128 + u_ * 16)); \
            int gm_ = m0 + r_; \
            if (gm_ < M) { \
                CP_ASYNC16(st_ + T_AH + sw_, (const char*)(Ah + (size_t)gm_ * K + k0_) + u_ * 16); \
                CP_ASYNC16(st_ + T_AL + sw_, (const char*)(Al + (size_t)gm_ * K + k0_) + u_ * 16); \
            } else { \
                STS_ZERO16(st_ + T_AH + sw_); \
                STS_ZERO16(st_ + T_AL + sw_); \
            } \
            int gn_ = n0 + r_; \
            CP_ASYNC16(st_ + T_BH + sw_, (const char*)(Bh + (size_t)gn_ * K + k0_) + u_ * 16); \
            CP_ASYNC16(st_ + T_BL + sw_, (const char*)(Bl + (size_t)gn_ * K + k0_) + u_ * 16); \
        } \
        CP_COMMIT(); \
    } while (0)

    LOAD_STAGE(0);

    const int q8 = lid >> 3, lr = lid & 7;   // ldmatrix quad / row-in-quad

    for (int cc = 0; cc < NC; cc++) {
        __syncthreads();                      // all warps done with buffer (cc+1)&1
        if (cc + 1 < NC) { LOAD_STAGE(cc + 1); } else { CP_COMMIT(); }
        CP_WAIT1();                           // chunk cc resident
        __syncthreads();

        const uint32_t st = sb + (cc & 1) * STG;
#pragma unroll
        for (int ks = 0; ks < 4; ks++) {
            const int kb = ks * 32;           // 16 bf16 = 32 bytes per k-step
            uint32_t ah[2][4], al[2][4], bh[8][2], bl[8][2];
            // A fragments: q0=(rows0-7,kb) q1=(rows8-15,kb) q2=(rows0-7,kb+16) q3=(rows8-15,kb+16)
#pragma unroll
            for (int mi = 0; mi < 2; mi++) {
                uint32_t off = SWZ((uint32_t)(
                    (wm * 32 + mi * 16 + lr + (q8 & 1) * 8) * 128 + kb + (q8 >> 1) * 16));
                ldsm4(ah[mi], st + T_AH + off);
                ldsm4(al[mi], st + T_AL + off);
            }
            // B fragments: q0=(n0-7,kb) q1=(n0-7,kb+16) q2=(n8-15,kb) q3=(n8-15,kb+16)
#pragma unroll
            for (int njp = 0; njp < 4; njp++) {
                uint32_t off = SWZ((uint32_t)(
                    (wn * 64 + njp * 16 + lr + (q8 >> 1) * 8) * 128 + kb + (q8 & 1) * 16));
                uint32_t t0[4], t1[4];
                ldsm4(t0, st + T_BH + off);
                ldsm4(t1, st + T_BL + off);
                bh[2 * njp][0] = t0[0]; bh[2 * njp][1] = t0[1];
                bh[2 * njp + 1][0] = t0[2]; bh[2 * njp + 1][1] = t0[3];
                bl[2 * njp][0] = t1[0]; bl[2 * njp][1] = t1[1];
                bl[2 * njp + 1][0] = t1[2]; bl[2 * njp + 1][1] = t1[3];
            }
#pragma unroll
            for (int mi = 0; mi < 2; mi++)
#pragma unroll
                for (int nj = 0; nj < 8; nj++) {
                    mma16816(c[mi][nj], ah[mi], bh[nj]);   // hi*hi
                    mma16816(c[mi][nj], ah[mi], bl[nj]);   // hi*lo
                    mma16816(c[mi][nj], al[mi], bh[nj]);   // lo*hi
                }
        }
    }

    // ---- epilogue: += bias, fp32 stores ----
    const int lr4 = lid >> 2, lc = (lid & 3) * 2;
    const float* __restrict__ bias = p.bias[z];
    float* __restrict__ C = p.C[z];
#pragma unroll
    for (int mi = 0; mi < 2; mi++) {
        int row = m0 + wm * 32 + mi * 16 + lr4;
#pragma unroll
        for (int nj = 0; nj < 8; nj++) {
            int col = n0 + wn * 64 + nj * 8 + lc;
            float2 b2 = *(const float2*)(bias + col);
            if (row < M) {
                float2 o = make_float2(c[mi][nj][0] + b2.x, c[mi][nj][1] + b2.y);
                *(float2*)(C + (size_t)row * N + col) = o;
            }
            if (row + 8 < M) {
                float2 o = make_float2(c[mi][nj][2] + b2.x, c[mi][nj][3] + b2.y);
                *(float2*)(C + (size_t)(row + 8) * N + col) = o;
            }
        }
    }
}

// ---------------------------------------------------------------------------
// Fused cross-attention (fp32, unchanged — R1-verified)
// ---------------------------------------------------------------------------
__global__ __launch_bounds__(128)
void attn32(const float* __restrict__ Q, const float* __restrict__ Kmat,
            const float* __restrict__ Vmat, float* __restrict__ O,
            const float* __restrict__ wptr, int accumulate)
{
    const int h = blockIdx.y;
    const int qBase = blockIdx.x * 32;
    const int t = threadIdx.x;
    const int r = t >> 2;
    const int g = t & 3;
    const int c0 = g * 16;

    __shared__ float q_sm[32][68];
    __shared__ float kv_sm[64][68];
    __shared__ float p_sm[32][68];

#pragma unroll
    for (int i = 0; i < 4; i++) {
        int f = i * 128 + t;
        int row = f >> 4;
        int e4 = (f & 15) * 4;
        float4 v4 = *reinterpret_cast<const float4*>(
            Q + (size_t)(qBase + row) * DINNER + h * EDIM + e4);
        *reinterpret_cast<float4*>(&q_sm[row][e4]) = v4;
    }

    float acc[16];
#pragma unroll
    for (int j = 0; j < 16; j++) acc[j] = 0.f;
    float m_run = -INFINITY;
    float lsum = 0.f;
    const float scale = 0.125f;

    for (int s0 = 0; s0 < SEQ_S; s0 += 64) {
        __syncthreads();
#pragma unroll
        for (int i = 0; i < 8; i++) {
            int f = i * 128 + t;
            int srow = f >> 4;
            int e4 = (f & 15) * 4;
            float4 v4 = make_float4(0.f, 0.f, 0.f, 0.f);
            if (s0 + srow < SEQ_S)
                v4 = *reinterpret_cast<const float4*>(
                    Kmat + (size_t)(s0 + srow) * DINNER + h * EDIM + e4);
            *reinterpret_cast<float4*>(&kv_sm[srow][e4]) = v4;
        }
        __syncthreads();

        float sc[16];
#pragma unroll
        for (int i = 0; i < 16; i++) sc[i] = 0.f;
#pragma unroll
        for (int e0 = 0; e0 < 64; e0 += 4) {
            float4 qv = *reinterpret_cast<const float4*>(&q_sm[r][e0]);
#pragma unroll
            for (int i = 0; i < 16; i++) {
                float4 kv4 = *reinterpret_cast<const float4*>(&kv_sm[g + 4 * i][e0]);
                sc[i] += qv.x * kv4.x + qv.y * kv4.y + qv.z * kv4.z + qv.w * kv4.w;
            }
        }
        float mloc = -INFINITY;
#pragma unroll
        for (int i = 0; i < 16; i++) {
            sc[i] *= scale;
            if (s0 + g + 4 * i >= SEQ_S) sc[i] = -INFINITY;
            mloc = fmaxf(mloc, sc[i]);
        }
        mloc = fmaxf(mloc, __shfl_xor_sync(0xffffffffu, mloc, 1));
        mloc = fmaxf(mloc, __shfl_xor_sync(0xffffffffu, mloc, 2));

        float m_new = fmaxf(m_run, mloc);
        float corr = __expf(m_run - m_new);
        m_run = m_new;
        lsum *= corr;
#pragma unroll
        for (int j = 0; j < 16; j++) acc[j] *= corr;

        float ls = 0.f;
#pragma unroll
        for (int i = 0; i < 16; i++) {
            float p = __expf(sc[i] - m_new);
            ls += p;
            p_sm[r][g + 4 * i] = p;
        }
        ls += __shfl_xor_sync(0xffffffffu, ls, 1);
        ls += __shfl_xor_sync(0xffffffffu, ls, 2);
        lsum += ls;

        __syncthreads();
#pragma unroll
        for (int i = 0; i < 8; i++) {
            int f = i * 128 + t;
            int srow = f >> 4;
            int e4 = (f & 15) * 4;
            float4 v4 = make_float4(0.f, 0.f, 0.f, 0.f);
            if (s0 + srow < SEQ_S)
                v4 = *reinterpret_cast<const float4*>(
                    Vmat + (size_t)(s0 + srow) * DINNER + h * EDIM + e4);
            *reinterpret_cast<float4*>(&kv_sm[srow][e4]) = v4;
        }
        __syncthreads();

#pragma unroll 4
        for (int s = 0; s < 64; s++) {
            float p = p_sm[r][s];
            float4 v0 = *reinterpret_cast<const float4*>(&kv_sm[s][c0 + 0]);
            float4 v1 = *reinterpret_cast<const float4*>(&kv_sm[s][c0 + 4]);
            float4 v2 = *reinterpret_cast<const float4*>(&kv_sm[s][c0 + 8]);
            float4 v3 = *reinterpret_cast<const float4*>(&kv_sm[s][c0 + 12]);
            acc[0]  += p * v0.x; acc[1]  += p * v0.y; acc[2]  += p * v0.z; acc[3]  += p * v0.w;
            acc[4]  += p * v1.x; acc[5]  += p * v1.y; acc[6]  += p * v1.z; acc[7]  += p * v1.w;
            acc[8]  += p * v2.x; acc[9]  += p * v2.y; acc[10] += p * v2.z; acc[11] += p * v2.w;
            acc[12] += p * v3.x; acc[13] += p * v3.y; acc[14] += p * v3.z; acc[15] += p * v3.w;
        }
    }

    const float w = *wptr;
    const float inv = w / lsum;
    float* outp = O + (size_t)(qBase + r) * DINNER + h * EDIM + c0;
#pragma unroll
    for (int j = 0; j < 16; j += 4) {
        float4 o;
        o.x = acc[j + 0] * inv;
        o.y = acc[j + 1] * inv;
        o.z = acc[j + 2] * inv;
        o.w = acc[j + 3] * inv;
        if (accumulate) {
            float4 prev = *reinterpret_cast<float4*>(outp + j);
            o.x += prev.x; o.y += prev.y; o.z += prev.z; o.w += prev.w;
        }
        *reinterpret_cast<float4*>(outp + j) = o;
    }
}

// ---------------------------------------------------------------------------
// Launch
// ---------------------------------------------------------------------------
extern "C" void kernel_launch(void* const* d_in, const int* in_sizes, int n_in,
                              void* d_out, int out_size)
{
    const float* target = (const float*)d_in[0];
    const float* source = (const float*)d_in[1];
    const float* value  = (const float*)d_in[2];
    const float* bq_s = (const float*)d_in[4];
    const float* bk_s = (const float*)d_in[6];
    const float* bv_s = (const float*)d_in[8];
    const float* bq_l = (const float*)d_in[10];
    const float* bk_l = (const float*)d_in[12];
    const float* bv_l = (const float*)d_in[14];
    const float* bo   = (const float*)d_in[16];
    const float* Wq_s = (const float*)d_in[3];
    const float* Wk_s = (const float*)d_in[5];
    const float* Wv_s = (const float*)d_in[7];
    const float* Wq_l = (const float*)d_in[9];
    const float* Wk_l = (const float*)d_in[11];
    const float* Wv_l = (const float*)d_in[13];
    const float* Wo   = (const float*)d_in[15];
    const float* alpha = (const float*)d_in[17];
    const float* beta  = (const float*)d_in[18];
    float* out = (float*)d_out;

    float *qs, *ql, *ks, *vs, *kl, *vl, *attn;
    cudaGetSymbolAddress((void**)&qs,   g_qs);
    cudaGetSymbolAddress((void**)&ql,   g_ql);
    cudaGetSymbolAddress((void**)&ks,   g_ks);
    cudaGetSymbolAddress((void**)&vs,   g_vs);
    cudaGetSymbolAddress((void**)&kl,   g_kl);
    cudaGetSymbolAddress((void**)&vl,   g_vl);
    cudaGetSymbolAddress((void**)&attn, g_attn);

    __nv_bfloat16 *th, *tl, *sh, *sl, *vh, *vl2, *ah, *al;
    cudaGetSymbolAddress((void**)&th,  g_th);  cudaGetSymbolAddress((void**)&tl,  g_tl);
    cudaGetSymbolAddress((void**)&sh,  g_sh);  cudaGetSymbolAddress((void**)&sl,  g_sl);
    cudaGetSymbolAddress((void**)&vh,  g_vh);  cudaGetSymbolAddress((void**)&vl2, g_vl2);
    cudaGetSymbolAddress((void**)&ah,  g_ah);  cudaGetSymbolAddress((void**)&al,  g_al);

    __nv_bfloat16 *wqsh, *wqsl, *wqlh, *wqll, *wksh, *wksl, *wvsh, *wvsl;
    __nv_bfloat16 *wklh, *wkll, *wvlh, *wvll, *woh, *wol;
    cudaGetSymbolAddress((void**)&wqsh, g_wqsh); cudaGetSymbolAddress((void**)&wqsl, g_wqsl);
    cudaGetSymbolAddress((void**)&wqlh, g_wqlh); cudaGetSymbolAddress((void**)&wqll, g_wqll);
    cudaGetSymbolAddress((void**)&wksh, g_wksh); cudaGetSymbolAddress((void**)&wksl, g_wksl);
    cudaGetSymbolAddress((void**)&wvsh, g_wvsh); cudaGetSymbolAddress((void**)&wvsl, g_wvsl);
    cudaGetSymbolAddress((void**)&wklh, g_wklh); cudaGetSymbolAddress((void**)&wkll, g_wkll);
    cudaGetSymbolAddress((void**)&wvlh, g_wvlh); cudaGetSymbolAddress((void**)&wvll, g_wvll);
    cudaGetSymbolAddress((void**)&woh,  g_woh);  cudaGetSymbolAddress((void**)&wol,  g_wol);

    cudaFuncSetAttribute(gemm_hmma, cudaFuncAttributeMaxDynamicSharedMemorySize, GEMM_SMEM);

    // --- prepass: split activations ---
    split_f32<<<2048, 256>>>(target, th, tl, BL * DMODEL);
    split_f32<<<1024, 256>>>(source, sh, sl, SEQ_S * DLLM);
    split_f32<<<1024, 256>>>(value,  vh, vl2, SEQ_S * DLLM);

    // --- prepass: split + transpose weights ---
    dim3 tb(32, 8);
    split_transpose<<<dim3(DINNER / 32, DMODEL / 32), tb>>>(Wq_s, wqsh, wqsl, DMODEL, DINNER);
    split_transpose<<<dim3(DINNER / 32, DMODEL / 32), tb>>>(Wq_l, wqlh, wqll, DMODEL, DINNER);
    split_transpose<<<dim3(DINNER / 32, DLLM / 32),   tb>>>(Wk_s, wksh, wksl, DLLM, DINNER);
    split_transpose<<<dim3(DINNER / 32, DLLM / 32),   tb>>>(Wv_s, wvsh, wvsl, DLLM, DINNER);
    split_transpose<<<dim3(DINNER / 32, DLLM / 32),   tb>>>(Wk_l, wklh, wkll, DLLM, DINNER);
    split_transpose<<<dim3(DINNER / 32, DLLM / 32),   tb>>>(Wv_l, wvlh, wvll, DLLM, DINNER);
    split_transpose<<<dim3(DLLM / 32, DINNER / 32),   tb>>>(Wo,   woh,  wol,  DINNER, DLLM);

    // --- Q projections (batched: qs, ql) ---
    {
        Batch p = {};
        p.Ah[0] = th; p.Al[0] = tl; p.Bh[0] = wqsh; p.Bl[0] = wqsl; p.bias[0] = bq_s; p.C[0] = qs;
        p.Ah[1] = th; p.Al[1] = tl; p.Bh[1] = wqlh; p.Bl[1] = wqll; p.bias[1] = bq_l; p.C[1] = ql;
        dim3 g(DINNER / 128, BL / 128, 2);           // (8, 64, 2)
        gemm_hmma<<<g, 256, GEMM_SMEM>>>(p, BL, DINNER, DMODEL);
    }
    // --- KV projections (batched: ks, vs, kl, vl) ---
    {
        Batch p = {};
        p.Ah[0] = sh; p.Al[0] = sl;  p.Bh[0] = wksh; p.Bl[0] = wksl; p.bias[0] = bk_s; p.C[0] = ks;
        p.Ah[1] = vh; p.Al[1] = vl2; p.Bh[1] = wvsh; p.Bl[1] = wvsl; p.bias[1] = bv_s; p.C[1] = vs;
        p.Ah[2] = sh; p.Al[2] = sl;  p.Bh[2] = wklh; p.Bl[2] = wkll; p.bias[2] = bk_l; p.C[2] = kl;
        p.Ah[3] = vh; p.Al[3] = vl2; p.Bh[3] = wvlh; p.Bl[3] = wvll; p.bias[3] = bv_l; p.C[3] = vl;
        dim3 g(DINNER / 128, (SEQ_S + 127) / 128, 4); // (8, 8, 4)
        gemm_hmma<<<g, 256, GEMM_SMEM>>>(p, SEQ_S, DINNER, DLLM);
    }

    // --- attention (fp32) ---
    dim3 ga(BL / 32, NHEAD);
    attn32<<<ga, 128>>>(qs, ks, vs, attn, alpha, 0);
    attn32<<<ga, 128>>>(ql, kl, vl, attn, beta, 1);

    // --- split attn output, final projection ---
    split_f32<<<2048, 256>>>(attn, ah, al, BL * DINNER);
    {
        Batch p = {};
        p.Ah[0] = ah; p.Al[0] = al; p.Bh[0] = woh; p.Bl[0] = wol; p.bias[0] = bo; p.C[0] = out;
        dim3 g(DLLM / 128, BL / 128, 1);             // (32, 64, 1)
        gemm_hmma<<<g, 256, GEMM_SMEM>>>(p, BL, DLLM, DINNER);
    }
}

// round 4
// speedup vs baseline: 6.7344x; 4.1018x over previous
#include <cuda_runtime.h>
#include <cuda_bf16.h>
#include <math.h>
#include <stdint.h>

// ---------------------------------------------------------------------------
// Problem constants: B=8, L=1024, d_model=1024, S=1000, d_llm=4096, H=16, E=64
// ---------------------------------------------------------------------------
#define BL     8192
#define DMODEL 1024
#define DLLM   4096
#define DINNER 1024
#define SEQ_S  1000
#define NHEAD  16
#define EDIM   64

// ---------------------------------------------------------------------------
// Portable PTX helpers (base compute_103 target — NO tcgen05)
// ---------------------------------------------------------------------------
__device__ __forceinline__ uint32_t smem_u32(const void* p) {
    uint32_t a;
    asm("{ .reg .u64 t; cvta.to.shared.u64 t, %1; cvt.u32.u64 %0, t; }"
        : "=r"(a) : "l"(p));
    return a;
}

#define SWZ(o) ((o) ^ (((o) >> 3) & 0x70))   // Swizzle<3,4,3> on 128B rows

#define CP_ASYNC16(dst, src) \
    asm volatile("cp.async.cg.shared.global [%0], [%1], 16;\n" :: "r"(dst), "l"(src))
#define CP_COMMIT() asm volatile("cp.async.commit_group;\n" ::: "memory")
#define CP_WAIT1()  asm volatile("cp.async.wait_group 1;\n" ::: "memory")
#define CP_WAIT0()  asm volatile("cp.async.wait_group 0;\n" ::: "memory")
#define STS_ZERO16(addr) \
    asm volatile("st.shared.v4.b32 [%0], {%1,%1,%1,%1};\n" :: "r"(addr), "r"(0u) : "memory")

__device__ __forceinline__ void ldsm4(uint32_t* r, uint32_t a) {
    asm volatile("ldmatrix.sync.aligned.m8n8.x4.shared.b16 {%0,%1,%2,%3}, [%4];\n"
        : "=r"(r[0]), "=r"(r[1]), "=r"(r[2]), "=r"(r[3]) : "r"(a));
}
__device__ __forceinline__ void ldsm4t(uint32_t* r, uint32_t a) {
    asm volatile("ldmatrix.sync.aligned.m8n8.x4.trans.shared.b16 {%0,%1,%2,%3}, [%4];\n"
        : "=r"(r[0]), "=r"(r[1]), "=r"(r[2]), "=r"(r[3]) : "r"(a));
}
__device__ __forceinline__ void mma16816(float* c, const uint32_t* a,
                                         uint32_t b0, uint32_t b1) {
    asm volatile(
        "mma.sync.aligned.m16n8k16.row.col.f32.bf16.bf16.f32 "
        "{%0,%1,%2,%3}, {%4,%5,%6,%7}, {%8,%9}, {%0,%1,%2,%3};\n"
        : "+f"(c[0]), "+f"(c[1]), "+f"(c[2]), "+f"(c[3])
        : "r"(a[0]), "r"(a[1]), "r"(a[2]), "r"(a[3]), "r"(b0), "r"(b1));
}

// pack two floats to bf16x2 hi + residual bf16x2 lo
__device__ __forceinline__ void pack_split(float a, float b, uint32_t& hi, uint32_t& lo) {
    __nv_bfloat162 h = __floats2bfloat162_rn(a, b);
    float ra = a - __bfloat162float(h.x);
    float rb = b - __bfloat162float(h.y);
    __nv_bfloat162 l = __floats2bfloat162_rn(ra, rb);
    hi = *reinterpret_cast<uint32_t*>(&h);
    lo = *reinterpret_cast<uint32_t*>(&l);
}

// ---------------------------------------------------------------------------
// Scratch (device globals — no allocation allowed)
// ---------------------------------------------------------------------------
// bf16 split activations (inputs)
__device__ __nv_bfloat16 g_th[BL * DMODEL],  g_tl[BL * DMODEL];
__device__ __nv_bfloat16 g_sh[SEQ_S * DLLM], g_sl[SEQ_S * DLLM];
__device__ __nv_bfloat16 g_vh[SEQ_S * DLLM], g_vl2[SEQ_S * DLLM];
// bf16 split projections
__device__ __nv_bfloat16 g_qsh[BL * DINNER],    g_qsl[BL * DINNER];
__device__ __nv_bfloat16 g_qlh[BL * DINNER],    g_qll[BL * DINNER];
__device__ __nv_bfloat16 g_ksh[SEQ_S * DINNER], g_ksl[SEQ_S * DINNER];
__device__ __nv_bfloat16 g_vsh[SEQ_S * DINNER], g_vsl[SEQ_S * DINNER];
__device__ __nv_bfloat16 g_klh[SEQ_S * DINNER], g_kll[SEQ_S * DINNER];
__device__ __nv_bfloat16 g_vlh[SEQ_S * DINNER], g_vll[SEQ_S * DINNER];
// attention output (bf16 split)
__device__ __nv_bfloat16 g_ah[BL * DINNER], g_al[BL * DINNER];
// bf16 split transposed weights [N, K]
__device__ __nv_bfloat16 g_wqsh[DINNER * DMODEL], g_wqsl[DINNER * DMODEL];
__device__ __nv_bfloat16 g_wqlh[DINNER * DMODEL], g_wqll[DINNER * DMODEL];
__device__ __nv_bfloat16 g_wksh[DINNER * DLLM],   g_wksl[DINNER * DLLM];
__device__ __nv_bfloat16 g_wvsh[DINNER * DLLM],   g_wvsl[DINNER * DLLM];
__device__ __nv_bfloat16 g_wklh[DINNER * DLLM],   g_wkll[DINNER * DLLM];
__device__ __nv_bfloat16 g_wvlh[DINNER * DLLM],   g_wvll[DINNER * DLLM];
__device__ __nv_bfloat16 g_woh[DLLM * DINNER],    g_wol[DLLM * DINNER];

// ---------------------------------------------------------------------------
// Prepass kernels
// ---------------------------------------------------------------------------
__global__ void split_f32(const float* __restrict__ x, __nv_bfloat16* __restrict__ hi,
                          __nv_bfloat16* __restrict__ lo, int n)
{
    int i = blockIdx.x * blockDim.x + threadIdx.x;
    int stride = gridDim.x * blockDim.x;
    for (; i < n; i += stride) {
        float v = x[i];
        __nv_bfloat16 h = __float2bfloat16(v);
        hi[i] = h;
        lo[i] = __float2bfloat16(v - __bfloat162float(h));
    }
}

__global__ void split_transpose(const float* __restrict__ W, __nv_bfloat16* __restrict__ Th,
                                __nv_bfloat16* __restrict__ Tl, int K, int N)
{
    __shared__ float t[32][33];
    int n0 = blockIdx.x * 32, k0 = blockIdx.y * 32;
    int tx = threadIdx.x, ty = threadIdx.y;  // 32 x 8
#pragma unroll
    for (int i = 0; i < 32; i += 8)
        t[ty + i][tx] = W[(size_t)(k0 + ty + i) * N + n0 + tx];
    __syncthreads();
#pragma unroll
    for (int i = 0; i < 32; i += 8) {
        int n = n0 + ty + i;
        float v = t[tx][ty + i];
        __nv_bfloat16 h = __float2bfloat16(v);
        Th[(size_t)n * K + k0 + tx] = h;
        Tl[(size_t)n * K + k0 + tx] = __float2bfloat16(v - __bfloat162float(h));
    }
}

// ---------------------------------------------------------------------------
// HMMA GEMM (bf16 split-2, 3 MMA terms), epilogue fp32 OR bf16-split
// ---------------------------------------------------------------------------
struct Batch {
    const __nv_bfloat16 *Ah[4], *Al[4], *Bh[4], *Bl[4];
    const float* bias[4];
    float* C[4];
    __nv_bfloat16 *Ch[4], *Cl[4];
    int obf;   // 1 -> write bf16 split to Ch/Cl
};

#define STG      65536
#define T_AH     0
#define T_AL     16384
#define T_BH     32768
#define T_BL     49152
#define GEMM_SMEM (2 * STG)

__global__ __launch_bounds__(256)
void gemm_hmma(Batch p, int M, int N, int K)
{
    extern __shared__ __align__(1024) char smem[];
    const int z = blockIdx.z;
    const __nv_bfloat16* __restrict__ Ah = p.Ah[z];
    const __nv_bfloat16* __restrict__ Al = p.Al[z];
    const __nv_bfloat16* __restrict__ Bh = p.Bh[z];
    const __nv_bfloat16* __restrict__ Bl = p.Bl[z];

    const int tid = threadIdx.x;
    const int wid = tid >> 5, lid = tid & 31;
    const int wm = wid & 3, wn = wid >> 2;
    const int m0 = blockIdx.y * 128, n0 = blockIdx.x * 128;
    const uint32_t sb = smem_u32(smem);

    float c[2][8][4];
#pragma unroll
    for (int i = 0; i < 2; i++)
#pragma unroll
        for (int j = 0; j < 8; j++)
#pragma unroll
            for (int q = 0; q < 4; q++) c[i][j][q] = 0.f;

    const int NC = K >> 6;

#define LOAD_STAGE(cchunk) do { \
        const uint32_t st_ = sb + ((cchunk) & 1) * STG; \
        const int k0_ = (cchunk) << 6; \
        _Pragma("unroll") \
        for (int i_ = 0; i_ < 4; i_++) { \
            int idx_ = i_ * 256 + tid; \
            int r_ = idx_ >> 3, u_ = idx_ & 7; \
            uint32_t sw_ = SWZ((uint32_t)(r_ * 128 + u_ * 16)); \
            int gm_ = m0 + r_; \
            if (gm_ < M) { \
                CP_ASYNC16(st_ + T_AH + sw_, (const char*)(Ah + (size_t)gm_ * K + k0_) + u_ * 16); \
                CP_ASYNC16(st_ + T_AL + sw_, (const char*)(Al + (size_t)gm_ * K + k0_) + u_ * 16); \
            } else { \
                STS_ZERO16(st_ + T_AH + sw_); \
                STS_ZERO16(st_ + T_AL + sw_); \
            } \
            int gn_ = n0 + r_; \
            CP_ASYNC16(st_ + T_BH + sw_, (const char*)(Bh + (size_t)gn_ * K + k0_) + u_ * 16); \
            CP_ASYNC16(st_ + T_BL + sw_, (const char*)(Bl + (size_t)gn_ * K + k0_) + u_ * 16); \
        } \
        CP_COMMIT(); \
    } while (0)

    LOAD_STAGE(0);

    const int q8 = lid >> 3, lr = lid & 7;

    for (int cc = 0; cc < NC; cc++) {
        __syncthreads();
        if (cc + 1 < NC) { LOAD_STAGE(cc + 1); } else { CP_COMMIT(); }
        CP_WAIT1();
        __syncthreads();

        const uint32_t st = sb + (cc & 1) * STG;
#pragma unroll
        for (int ks = 0; ks < 4; ks++) {
            const int kb = ks * 32;
            uint32_t ah[2][4], al[2][4], bh[8][2], bl[8][2];
#pragma unroll
            for (int mi = 0; mi < 2; mi++) {
                uint32_t off = SWZ((uint32_t)(
                    (wm * 32 + mi * 16 + lr + (q8 & 1) * 8) * 128 + kb + (q8 >> 1) * 16));
                ldsm4(ah[mi], st + T_AH + off);
                ldsm4(al[mi], st + T_AL + off);
            }
#pragma unroll
            for (int njp = 0; njp < 4; njp++) {
                uint32_t off = SWZ((uint32_t)(
                    (wn * 64 + njp * 16 + lr + (q8 >> 1) * 8) * 128 + kb + (q8 & 1) * 16));
                uint32_t t0[4], t1[4];
                ldsm4(t0, st + T_BH + off);
                ldsm4(t1, st + T_BL + off);
                bh[2 * njp][0] = t0[0]; bh[2 * njp][1] = t0[1];
                bh[2 * njp + 1][0] = t0[2]; bh[2 * njp + 1][1] = t0[3];
                bl[2 * njp][0] = t1[0]; bl[2 * njp][1] = t1[1];
                bl[2 * njp + 1][0] = t1[2]; bl[2 * njp + 1][1] = t1[3];
            }
#pragma unroll
            for (int mi = 0; mi < 2; mi++)
#pragma unroll
                for (int nj = 0; nj < 8; nj++) {
                    mma16816(c[mi][nj], ah[mi], bh[nj][0], bh[nj][1]);
                    mma16816(c[mi][nj], ah[mi], bl[nj][0], bl[nj][1]);
                    mma16816(c[mi][nj], al[mi], bh[nj][0], bh[nj][1]);
                }
        }
    }

    const int lr4 = lid >> 2, lc = (lid & 3) * 2;
    const float* __restrict__ bias = p.bias[z];
#pragma unroll
    for (int mi = 0; mi < 2; mi++) {
        int row = m0 + wm * 32 + mi * 16 + lr4;
#pragma unroll
        for (int nj = 0; nj < 8; nj++) {
            int col = n0 + wn * 64 + nj * 8 + lc;
            float2 b2 = *(const float2*)(bias + col);
            float v00 = c[mi][nj][0] + b2.x, v01 = c[mi][nj][1] + b2.y;
            float v10 = c[mi][nj][2] + b2.x, v11 = c[mi][nj][3] + b2.y;
            if (p.obf) {
                __nv_bfloat16* Ch = p.Ch[z];
                __nv_bfloat16* Cl = p.Cl[z];
                uint32_t h0, l0, h1, l1;
                pack_split(v00, v01, h0, l0);
                pack_split(v10, v11, h1, l1);
                if (row < M) {
                    *(uint32_t*)(Ch + (size_t)row * N + col) = h0;
                    *(uint32_t*)(Cl + (size_t)row * N + col) = l0;
                }
                if (row + 8 < M) {
                    *(uint32_t*)(Ch + (size_t)(row + 8) * N + col) = h1;
                    *(uint32_t*)(Cl + (size_t)(row + 8) * N + col) = l1;
                }
            } else {
                float* C = p.C[z];
                if (row < M)
                    *(float2*)(C + (size_t)row * N + col) = make_float2(v00, v01);
                if (row + 8 < M)
                    *(float2*)(C + (size_t)(row + 8) * N + col) = make_float2(v10, v11);
            }
        }
    }
}

// ---------------------------------------------------------------------------
// HMMA flash attention, both streams fused, bf16 split-2 (3 terms) everywhere.
// Block = 64 queries x 1 head, 4 warps (16 q rows each), S chunks of 64.
// ---------------------------------------------------------------------------
struct AttnParams {
    const __nv_bfloat16 *qh[2], *ql[2], *kh[2], *kl[2], *vh[2], *vl[2];
    const float *alpha, *beta;
    __nv_bfloat16 *oh, *ol;
};

#define ATT_STAGE 32768
#define A_KH 0
#define A_KL 8192
#define A_VH 16384
#define A_VL 24576
#define ATT_SMEM (2 * ATT_STAGE)   // 64 KB
#define NCH 16                     // ceil(1000/64)
#define SOFTMAX_SCALE 0.125f

__global__ __launch_bounds__(128)
void attn_mma(AttnParams p)
{
    extern __shared__ __align__(1024) char smem[];
    const uint32_t sb = smem_u32(smem);
    const int tid = threadIdx.x;
    const int w = tid >> 5, lid = tid & 31;
    const int q8 = lid >> 3, lr = lid & 7;
    const int h = blockIdx.y;
    const int qbase = blockIdx.x * 64;
    const int colbase = h * EDIM;

    const float alpha = *p.alpha;
    const float beta  = *p.beta;

    float osave[8][4];

    for (int st = 0; st < 2; st++) {
        const __nv_bfloat16* __restrict__ qhp = p.qh[st];
        const __nv_bfloat16* __restrict__ qlp = p.ql[st];
        const __nv_bfloat16* __restrict__ khp = p.kh[st];
        const __nv_bfloat16* __restrict__ klp = p.kl[st];
        const __nv_bfloat16* __restrict__ vhp = p.vh[st];
        const __nv_bfloat16* __restrict__ vlp = p.vl[st];

        // ---- stage Q (64x64 hi/lo) into stage0 K area, load fragments ----
#pragma unroll
        for (int i = 0; i < 4; i++) {
            int idx = i * 128 + tid;            // 512 = 64 rows x 8 chunks
            int r = idx >> 3, u = idx & 7;
            uint32_t sw = SWZ((uint32_t)(r * 128 + u * 16));
            CP_ASYNC16(sb + A_KH + sw,
                       (const char*)(qhp + (size_t)(qbase + r) * DINNER + colbase) + u * 16);
            CP_ASYNC16(sb + A_KL + sw,
                       (const char*)(qlp + (size_t)(qbase + r) * DINNER + colbase) + u * 16);
        }
        CP_COMMIT();
        CP_WAIT0();
        __syncthreads();

        uint32_t qfh[4][4], qfl[4][4];
#pragma unroll
        for (int ks = 0; ks < 4; ks++) {
            uint32_t off = SWZ((uint32_t)(
                (w * 16 + lr + (q8 & 1) * 8) * 128 + ks * 32 + (q8 >> 1) * 16));
            ldsm4(qfh[ks], sb + A_KH + off);
            ldsm4(qfl[ks], sb + A_KL + off);
        }
        __syncthreads();

        float o[8][4];
#pragma unroll
        for (int t = 0; t < 8; t++)
#pragma unroll
            for (int i = 0; i < 4; i++) o[t][i] = 0.f;
        float m0r = -INFINITY, m1r = -INFINITY;
        float l0 = 0.f, l1 = 0.f;

        // ---- K/V chunk loader ----
#define LOAD_KV(cchunk) do { \
            const uint32_t stg_ = sb + ((cchunk) & 1) * ATT_STAGE; \
            const int s0_ = (cchunk) * 64; \
            _Pragma("unroll") \
            for (int i_ = 0; i_ < 4; i_++) { \
                int idx_ = i_ * 128 + tid; \
                int r_ = idx_ >> 3, u_ = idx_ & 7; \
                uint32_t sw_ = SWZ((uint32_t)(r_ * 128 + u_ * 16)); \
                if (s0_ + r_ < SEQ_S) { \
                    const size_t go_ = (size_t)(s0_ + r_) * DINNER + colbase; \
                    CP_ASYNC16(stg_ + A_KH + sw_, (const char*)(khp + go_) + u_ * 16); \
                    CP_ASYNC16(stg_ + A_KL + sw_, (const char*)(klp + go_) + u_ * 16); \
                    CP_ASYNC16(stg_ + A_VH + sw_, (const char*)(vhp + go_) + u_ * 16); \
                    CP_ASYNC16(stg_ + A_VL + sw_, (const char*)(vlp + go_) + u_ * 16); \
                } else { \
                    STS_ZERO16(stg_ + A_KH + sw_); \
                    STS_ZERO16(stg_ + A_KL + sw_); \
                    STS_ZERO16(stg_ + A_VH + sw_); \
                    STS_ZERO16(stg_ + A_VL + sw_); \
                } \
            } \
            CP_COMMIT(); \
        } while (0)

        LOAD_KV(0);

        for (int cc = 0; cc < NCH; cc++) {
            __syncthreads();
            if (cc + 1 < NCH) { LOAD_KV(cc + 1); } else { CP_COMMIT(); }
            CP_WAIT1();
            __syncthreads();
            const uint32_t stg = sb + (cc & 1) * ATT_STAGE;

            // ---- scores: S[16,64] = Q Kt (split-2, 3 terms) ----
            float s[8][4];
#pragma unroll
            for (int t = 0; t < 8; t++)
#pragma unroll
                for (int i = 0; i < 4; i++) s[t][i] = 0.f;

#pragma unroll
            for (int ks = 0; ks < 4; ks++) {
                uint32_t bh[8][2], bl[8][2];
#pragma unroll
                for (int njp = 0; njp < 4; njp++) {
                    uint32_t off = SWZ((uint32_t)(
                        (njp * 16 + lr + (q8 >> 1) * 8) * 128 + ks * 32 + (q8 & 1) * 16));
                    uint32_t t0[4], t1[4];
                    ldsm4(t0, stg + A_KH + off);
                    ldsm4(t1, stg + A_KL + off);
                    bh[2 * njp][0] = t0[0]; bh[2 * njp][1] = t0[1];
                    bh[2 * njp + 1][0] = t0[2]; bh[2 * njp + 1][1] = t0[3];
                    bl[2 * njp][0] = t1[0]; bl[2 * njp][1] = t1[1];
                    bl[2 * njp + 1][0] = t1[2]; bl[2 * njp + 1][1] = t1[3];
                }
#pragma unroll
                for (int t = 0; t < 8; t++) {
                    mma16816(s[t], qfh[ks], bh[t][0], bh[t][1]);
                    mma16816(s[t], qfh[ks], bl[t][0], bl[t][1]);
                    mma16816(s[t], qfl[ks], bh[t][0], bh[t][1]);
                }
            }

            // mask tail (chunk 15: s_local >= 40 -> tiles 5..7)
            if (cc == NCH - 1) {
#pragma unroll
                for (int t = 5; t < 8; t++)
#pragma unroll
                    for (int i = 0; i < 4; i++) s[t][i] = -1e30f;
            }

            // ---- online softmax (rows r = lid/4 and r+8) ----
            float ml0 = -1e30f, ml1 = -1e30f;
#pragma unroll
            for (int t = 0; t < 8; t++) {
                ml0 = fmaxf(ml0, fmaxf(s[t][0], s[t][1]));
                ml1 = fmaxf(ml1, fmaxf(s[t][2], s[t][3]));
            }
            ml0 = fmaxf(ml0, __shfl_xor_sync(0xffffffffu, ml0, 1));
            ml0 = fmaxf(ml0, __shfl_xor_sync(0xffffffffu, ml0, 2));
            ml1 = fmaxf(ml1, __shfl_xor_sync(0xffffffffu, ml1, 1));
            ml1 = fmaxf(ml1, __shfl_xor_sync(0xffffffffu, ml1, 2));

            float mn0 = fmaxf(m0r, ml0), mn1 = fmaxf(m1r, ml1);
            float c0 = __expf((m0r - mn0) * SOFTMAX_SCALE);
            float c1 = __expf((m1r - mn1) * SOFTMAX_SCALE);
            m0r = mn0; m1r = mn1;
            l0 *= c0; l1 *= c1;
#pragma unroll
            for (int t = 0; t < 8; t++) {
                o[t][0] *= c0; o[t][1] *= c0;
                o[t][2] *= c1; o[t][3] *= c1;
            }
#pragma unroll
            for (int t = 0; t < 8; t++) {
                float p0 = __expf((s[t][0] - mn0) * SOFTMAX_SCALE);
                float p1 = __expf((s[t][1] - mn0) * SOFTMAX_SCALE);
                float p2 = __expf((s[t][2] - mn1) * SOFTMAX_SCALE);
                float p3 = __expf((s[t][3] - mn1) * SOFTMAX_SCALE);
                l0 += p0 + p1; l1 += p2 + p3;
                s[t][0] = p0; s[t][1] = p1; s[t][2] = p2; s[t][3] = p3;
            }

            // ---- O += P V (split-2, 3 terms), V via ldmatrix.trans ----
#pragma unroll
            for (int ks = 0; ks < 4; ks++) {
                uint32_t pah[4], pal[4];
                pack_split(s[2 * ks][0],     s[2 * ks][1],     pah[0], pal[0]);
                pack_split(s[2 * ks][2],     s[2 * ks][3],     pah[1], pal[1]);
                pack_split(s[2 * ks + 1][0], s[2 * ks + 1][1], pah[2], pal[2]);
                pack_split(s[2 * ks + 1][2], s[2 * ks + 1][3], pah[3], pal[3]);
#pragma unroll
                for (int ep = 0; ep < 4; ep++) {
                    uint32_t off = SWZ((uint32_t)(
                        (ks * 16 + lr + (q8 & 1) * 8) * 128 + ep * 32 + (q8 >> 1) * 16));
                    uint32_t tv0[4], tv1[4];
                    ldsm4t(tv0, stg + A_VH + off);
                    ldsm4t(tv1, stg + A_VL + off);
                    mma16816(o[2 * ep],     pah, tv0[0], tv0[1]);
                    mma16816(o[2 * ep],     pah, tv1[0], tv1[1]);
                    mma16816(o[2 * ep],     pal, tv0[0], tv0[1]);
                    mma16816(o[2 * ep + 1], pah, tv0[2], tv0[3]);
                    mma16816(o[2 * ep + 1], pah, tv1[2], tv1[3]);
                    mma16816(o[2 * ep + 1], pal, tv0[2], tv0[3]);
                }
            }
        }

        // ---- finalize stream ----
        l0 += __shfl_xor_sync(0xffffffffu, l0, 1);
        l0 += __shfl_xor_sync(0xffffffffu, l0, 2);
        l1 += __shfl_xor_sync(0xffffffffu, l1, 1);
        l1 += __shfl_xor_sync(0xffffffffu, l1, 2);
        float wgt = (st == 0) ? alpha : beta;
        float f0 = wgt / l0, f1 = wgt / l1;
        if (st == 0) {
#pragma unroll
            for (int t = 0; t < 8; t++) {
                osave[t][0] = o[t][0] * f0; osave[t][1] = o[t][1] * f0;
                osave[t][2] = o[t][2] * f1; osave[t][3] = o[t][3] * f1;
            }
        } else {
#pragma unroll
            for (int t = 0; t < 8; t++) {
                osave[t][0] += o[t][0] * f0; osave[t][1] += o[t][1] * f0;
                osave[t][2] += o[t][2] * f1; osave[t][3] += o[t][3] * f1;
            }
        }
        __syncthreads();   // all warps done with smem before next stream restages Q
    }

    // ---- write combined output as bf16 split ----
    const int r0 = qbase + w * 16 + (lid >> 2);
#pragma unroll
    for (int t = 0; t < 8; t++) {
        int col = colbase + t * 8 + (lid & 3) * 2;
        uint32_t h0, lo0, h1, lo1;
        pack_split(osave[t][0], osave[t][1], h0, lo0);
        pack_split(osave[t][2], osave[t][3], h1, lo1);
        *(uint32_t*)(p.oh + (size_t)r0 * DINNER + col) = h0;
        *(uint32_t*)(p.ol + (size_t)r0 * DINNER + col) = lo0;
        *(uint32_t*)(p.oh + (size_t)(r0 + 8) * DINNER + col) = h1;
        *(uint32_t*)(p.ol + (size_t)(r0 + 8) * DINNER + col) = lo1;
    }
}

// ---------------------------------------------------------------------------
// Launch
// ---------------------------------------------------------------------------
extern "C" void kernel_launch(void* const* d_in, const int* in_sizes, int n_in,
                              void* d_out, int out_size)
{
    const float* target = (const float*)d_in[0];
    const float* source = (const float*)d_in[1];
    const float* value  = (const float*)d_in[2];
    const float* Wq_s = (const float*)d_in[3];  const float* bq_s = (const float*)d_in[4];
    const float* Wk_s = (const float*)d_in[5];  const float* bk_s = (const float*)d_in[6];
    const float* Wv_s = (const float*)d_in[7];  const float* bv_s = (const float*)d_in[8];
    const float* Wq_l = (const float*)d_in[9];  const float* bq_l = (const float*)d_in[10];
    const float* Wk_l = (const float*)d_in[11]; const float* bk_l = (const float*)d_in[12];
    const float* Wv_l = (const float*)d_in[13]; const float* bv_l = (const float*)d_in[14];
    const float* Wo   = (const float*)d_in[15]; const float* bo   = (const float*)d_in[16];
    const float* alpha = (const float*)d_in[17];
    const float* beta  = (const float*)d_in[18];
    float* out = (float*)d_out;

    __nv_bfloat16 *th, *tl, *sh, *sl, *vh, *vl2, *ah, *al;
    cudaGetSymbolAddress((void**)&th,  g_th);  cudaGetSymbolAddress((void**)&tl,  g_tl);
    cudaGetSymbolAddress((void**)&sh,  g_sh);  cudaGetSymbolAddress((void**)&sl,  g_sl);
    cudaGetSymbolAddress((void**)&vh,  g_vh);  cudaGetSymbolAddress((void**)&vl2, g_vl2);
    cudaGetSymbolAddress((void**)&ah,  g_ah);  cudaGetSymbolAddress((void**)&al,  g_al);

    __nv_bfloat16 *qsh, *qsl, *qlh, *qll, *ksh, *ksl, *vsh, *vsl, *klh, *kll, *vlh, *vll;
    cudaGetSymbolAddress((void**)&qsh, g_qsh); cudaGetSymbolAddress((void**)&qsl, g_qsl);
    cudaGetSymbolAddress((void**)&qlh, g_qlh); cudaGetSymbolAddress((void**)&qll, g_qll);
    cudaGetSymbolAddress((void**)&ksh, g_ksh); cudaGetSymbolAddress((void**)&ksl, g_ksl);
    cudaGetSymbolAddress((void**)&vsh, g_vsh); cudaGetSymbolAddress((void**)&vsl, g_vsl);
    cudaGetSymbolAddress((void**)&klh, g_klh); cudaGetSymbolAddress((void**)&kll, g_kll);
    cudaGetSymbolAddress((void**)&vlh, g_vlh); cudaGetSymbolAddress((void**)&vll, g_vll);

    __nv_bfloat16 *wqsh, *wqsl, *wqlh, *wqll, *wksh, *wksl, *wvsh, *wvsl;
    __nv_bfloat16 *wklh, *wkll, *wvlh, *wvll, *woh, *wol;
    cudaGetSymbolAddress((void**)&wqsh, g_wqsh); cudaGetSymbolAddress((void**)&wqsl, g_wqsl);
    cudaGetSymbolAddress((void**)&wqlh, g_wqlh); cudaGetSymbolAddress((void**)&wqll, g_wqll);
    cudaGetSymbolAddress((void**)&wksh, g_wksh); cudaGetSymbolAddress((void**)&wksl, g_wksl);
    cudaGetSymbolAddress((void**)&wvsh, g_wvsh); cudaGetSymbolAddress((void**)&wvsl, g_wvsl);
    cudaGetSymbolAddress((void**)&wklh, g_wklh); cudaGetSymbolAddress((void**)&wkll, g_wkll);
    cudaGetSymbolAddress((void**)&wvlh, g_wvlh); cudaGetSymbolAddress((void**)&wvll, g_wvll);
    cudaGetSymbolAddress((void**)&woh,  g_woh);  cudaGetSymbolAddress((void**)&wol,  g_wol);

    cudaFuncSetAttribute(gemm_hmma, cudaFuncAttributeMaxDynamicSharedMemorySize, GEMM_SMEM);
    cudaFuncSetAttribute(attn_mma, cudaFuncAttributeMaxDynamicSharedMemorySize, ATT_SMEM);

    // --- prepass ---
    split_f32<<<2048, 256>>>(target, th, tl, BL * DMODEL);
    split_f32<<<1024, 256>>>(source, sh, sl, SEQ_S * DLLM);
    split_f32<<<1024, 256>>>(value,  vh, vl2, SEQ_S * DLLM);
    dim3 tb(32, 8);
    split_transpose<<<dim3(DINNER / 32, DMODEL / 32), tb>>>(Wq_s, wqsh, wqsl, DMODEL, DINNER);
    split_transpose<<<dim3(DINNER / 32, DMODEL / 32), tb>>>(Wq_l, wqlh, wqll, DMODEL, DINNER);
    split_transpose<<<dim3(DINNER / 32, DLLM / 32),   tb>>>(Wk_s, wksh, wksl, DLLM, DINNER);
    split_transpose<<<dim3(DINNER / 32, DLLM / 32),   tb>>>(Wv_s, wvsh, wvsl, DLLM, DINNER);
    split_transpose<<<dim3(DINNER / 32, DLLM / 32),   tb>>>(Wk_l, wklh, wkll, DLLM, DINNER);
    split_transpose<<<dim3(DINNER / 32, DLLM / 32),   tb>>>(Wv_l, wvlh, wvll, DLLM, DINNER);
    split_transpose<<<dim3(DLLM / 32, DINNER / 32),   tb>>>(Wo,   woh,  wol,  DINNER, DLLM);

    // --- Q projections -> bf16 split ---
    {
        Batch p = {};
        p.obf = 1;
        p.Ah[0] = th; p.Al[0] = tl; p.Bh[0] = wqsh; p.Bl[0] = wqsl; p.bias[0] = bq_s;
        p.Ch[0] = qsh; p.Cl[0] = qsl;
        p.Ah[1] = th; p.Al[1] = tl; p.Bh[1] = wqlh; p.Bl[1] = wqll; p.bias[1] = bq_l;
        p.Ch[1] = qlh; p.Cl[1] = qll;
        dim3 g(DINNER / 128, BL / 128, 2);
        gemm_hmma<<<g, 256, GEMM_SMEM>>>(p, BL, DINNER, DMODEL);
    }
    // --- KV projections -> bf16 split ---
    {
        Batch p = {};
        p.obf = 1;
        p.Ah[0] = sh; p.Al[0] = sl;  p.Bh[0] = wksh; p.Bl[0] = wksl; p.bias[0] = bk_s;
        p.Ch[0] = ksh; p.Cl[0] = ksl;
        p.Ah[1] = vh; p.Al[1] = vl2; p.Bh[1] = wvsh; p.Bl[1] = wvsl; p.bias[1] = bv_s;
        p.Ch[1] = vsh; p.Cl[1] = vsl;
        p.Ah[2] = sh; p.Al[2] = sl;  p.Bh[2] = wklh; p.Bl[2] = wkll; p.bias[2] = bk_l;
        p.Ch[2] = klh; p.Cl[2] = kll;
        p.Ah[3] = vh; p.Al[3] = vl2; p.Bh[3] = wvlh; p.Bl[3] = wvll; p.bias[3] = bv_l;
        p.Ch[3] = vlh; p.Cl[3] = vll;
        dim3 g(DINNER / 128, (SEQ_S + 127) / 128, 4);
        gemm_hmma<<<g, 256, GEMM_SMEM>>>(p, SEQ_S, DINNER, DLLM);
    }

    // --- fused dual-stream flash attention (HMMA) ---
    {
        AttnParams ap = {};
        ap.qh[0] = qsh; ap.ql[0] = qsl; ap.kh[0] = ksh; ap.kl[0] = ksl;
        ap.vh[0] = vsh; ap.vl[0] = vsl;
        ap.qh[1] = qlh; ap.ql[1] = qll; ap.kh[1] = klh; ap.kl[1] = kll;
        ap.vh[1] = vlh; ap.vl[1] = vll;
        ap.alpha = alpha; ap.beta = beta;
        ap.oh = ah; ap.ol = al;
        dim3 g(BL / 64, NHEAD);
        attn_mma<<<g, 128, ATT_SMEM>>>(ap);
    }

    // --- final projection (fp32 out) ---
    {
        Batch p = {};
        p.obf = 0;
        p.Ah[0] = ah; p.Al[0] = al; p.Bh[0] = woh; p.Bl[0] = wol; p.bias[0] = bo;
        p.C[0] = out;
        dim3 g(DLLM / 128, BL / 128, 1);
        gemm_hmma<<<g, 256, GEMM_SMEM>>>(p, BL, DLLM, DINNER);
    }
}

// round 5
// speedup vs baseline: 7.2557x; 1.0774x over previous
#include <cuda_runtime.h>
#include <cuda_bf16.h>
#include <math.h>
#include <stdint.h>

// ---------------------------------------------------------------------------
// Problem constants: B=8, L=1024, d_model=1024, S=1000, d_llm=4096, H=16, E=64
// ---------------------------------------------------------------------------
#define BL     8192
#define DMODEL 1024
#define DLLM   4096
#define DINNER 1024
#define SEQ_S  1000
#define NHEAD  16
#define EDIM   64

// ---------------------------------------------------------------------------
// Portable PTX helpers (base compute_103 target — NO tcgen05)
// ---------------------------------------------------------------------------
__device__ __forceinline__ uint32_t smem_u32(const void* p) {
    uint32_t a;
    asm("{ .reg .u64 t; cvta.to.shared.u64 t, %1; cvt.u32.u64 %0, t; }"
        : "=r"(a) : "l"(p));
    return a;
}

#define SWZ(o) ((o) ^ (((o) >> 3) & 0x70))   // Swizzle<3,4,3> on 128B rows

#define CP_ASYNC16(dst, src) \
    asm volatile("cp.async.cg.shared.global [%0], [%1], 16;\n" :: "r"(dst), "l"(src))
#define CP_COMMIT() asm volatile("cp.async.commit_group;\n" ::: "memory")
#define CP_WAIT1()  asm volatile("cp.async.wait_group 1;\n" ::: "memory")
#define CP_WAIT0()  asm volatile("cp.async.wait_group 0;\n" ::: "memory")
#define STS_ZERO16(addr) \
    asm volatile("st.shared.v4.b32 [%0], {%1,%1,%1,%1};\n" :: "r"(addr), "r"(0u) : "memory")

__device__ __forceinline__ void ldsm4(uint32_t* r, uint32_t a) {
    asm volatile("ldmatrix.sync.aligned.m8n8.x4.shared.b16 {%0,%1,%2,%3}, [%4];\n"
        : "=r"(r[0]), "=r"(r[1]), "=r"(r[2]), "=r"(r[3]) : "r"(a));
}
__device__ __forceinline__ void ldsm4t(uint32_t* r, uint32_t a) {
    asm volatile("ldmatrix.sync.aligned.m8n8.x4.trans.shared.b16 {%0,%1,%2,%3}, [%4];\n"
        : "=r"(r[0]), "=r"(r[1]), "=r"(r[2]), "=r"(r[3]) : "r"(a));
}
__device__ __forceinline__ void mma16816(float* c, const uint32_t* a,
                                         uint32_t b0, uint32_t b1) {
    asm volatile(
        "mma.sync.aligned.m16n8k16.row.col.f32.bf16.bf16.f32 "
        "{%0,%1,%2,%3}, {%4,%5,%6,%7}, {%8,%9}, {%0,%1,%2,%3};\n"
        : "+f"(c[0]), "+f"(c[1]), "+f"(c[2]), "+f"(c[3])
        : "r"(a[0]), "r"(a[1]), "r"(a[2]), "r"(a[3]), "r"(b0), "r"(b1));
}

// pack two floats to bf16x2 hi + residual bf16x2 lo
__device__ __forceinline__ void pack_split(float a, float b, uint32_t& hi, uint32_t& lo) {
    __nv_bfloat162 h = __floats2bfloat162_rn(a, b);
    float ra = a - __bfloat162float(h.x);
    float rb = b - __bfloat162float(h.y);
    __nv_bfloat162 l = __floats2bfloat162_rn(ra, rb);
    hi = *reinterpret_cast<uint32_t*>(&h);
    lo = *reinterpret_cast<uint32_t*>(&l);
}

// ---------------------------------------------------------------------------
// Scratch (device globals — no allocation allowed)
// ---------------------------------------------------------------------------
__device__ __nv_bfloat16 g_th[BL * DMODEL],  g_tl[BL * DMODEL];
__device__ __nv_bfloat16 g_sh[SEQ_S * DLLM], g_sl[SEQ_S * DLLM];
__device__ __nv_bfloat16 g_vh[SEQ_S * DLLM], g_vl2[SEQ_S * DLLM];
__device__ __nv_bfloat16 g_qsh[BL * DINNER],    g_qsl[BL * DINNER];
__device__ __nv_bfloat16 g_qlh[BL * DINNER],    g_qll[BL * DINNER];
__device__ __nv_bfloat16 g_ksh[SEQ_S * DINNER], g_ksl[SEQ_S * DINNER];
__device__ __nv_bfloat16 g_vsh[SEQ_S * DINNER], g_vsl[SEQ_S * DINNER];
__device__ __nv_bfloat16 g_klh[SEQ_S * DINNER], g_kll[SEQ_S * DINNER];
__device__ __nv_bfloat16 g_vlh[SEQ_S * DINNER], g_vll[SEQ_S * DINNER];
__device__ __nv_bfloat16 g_ah[BL * DINNER], g_al[BL * DINNER];
__device__ __nv_bfloat16 g_wqsh[DINNER * DMODEL], g_wqsl[DINNER * DMODEL];
__device__ __nv_bfloat16 g_wqlh[DINNER * DMODEL], g_wqll[DINNER * DMODEL];
__device__ __nv_bfloat16 g_wksh[DINNER * DLLM],   g_wksl[DINNER * DLLM];
__device__ __nv_bfloat16 g_wvsh[DINNER * DLLM],   g_wvsl[DINNER * DLLM];
__device__ __nv_bfloat16 g_wklh[DINNER * DLLM],   g_wkll[DINNER * DLLM];
__device__ __nv_bfloat16 g_wvlh[DINNER * DLLM],   g_wvll[DINNER * DLLM];
__device__ __nv_bfloat16 g_woh[DLLM * DINNER],    g_wol[DLLM * DINNER];

// ---------------------------------------------------------------------------
// Prepass kernels
// ---------------------------------------------------------------------------
__global__ void split_f32(const float* __restrict__ x, __nv_bfloat16* __restrict__ hi,
                          __nv_bfloat16* __restrict__ lo, int n)
{
    int i = blockIdx.x * blockDim.x + threadIdx.x;
    int stride = gridDim.x * blockDim.x;
    for (; i < n; i += stride) {
        float v = x[i];
        __nv_bfloat16 h = __float2bfloat16(v);
        hi[i] = h;
        lo[i] = __float2bfloat16(v - __bfloat162float(h));
    }
}

__global__ void split_transpose(const float* __restrict__ W, __nv_bfloat16* __restrict__ Th,
                                __nv_bfloat16* __restrict__ Tl, int K, int N)
{
    __shared__ float t[32][33];
    int n0 = blockIdx.x * 32, k0 = blockIdx.y * 32;
    int tx = threadIdx.x, ty = threadIdx.y;  // 32 x 8
#pragma unroll
    for (int i = 0; i < 32; i += 8)
        t[ty + i][tx] = W[(size_t)(k0 + ty + i) * N + n0 + tx];
    __syncthreads();
#pragma unroll
    for (int i = 0; i < 32; i += 8) {
        int n = n0 + ty + i;
        float v = t[tx][ty + i];
        __nv_bfloat16 h = __float2bfloat16(v);
        Th[(size_t)n * K + k0 + tx] = h;
        Tl[(size_t)n * K + k0 + tx] = __float2bfloat16(v - __bfloat162float(h));
    }
}

// ---------------------------------------------------------------------------
// HMMA GEMM (bf16 split-2, 3 MMA terms), epilogue fp32 OR bf16-split.
// Block tile 128(M) x 64(N), BK=64 (128B SW128 rows), 8 warps (4m x 2n),
// warp tile 32x32. 2-stage cp.async pipeline, 96KB smem -> 2 CTAs/SM.
// ---------------------------------------------------------------------------
struct Batch {
    const __nv_bfloat16 *Ah[4], *Al[4], *Bh[4], *Bl[4];
    const float* bias[4];
    float* C[4];
    __nv_bfloat16 *Ch[4], *Cl[4];
    int obf;
};

#define STG      49152          // 16K(AH)+16K(AL)+8K(BH)+8K(BL)
#define T_AH     0
#define T_AL     16384
#define T_BH     32768
#define T_BL     40960
#define GEMM_SMEM (2 * STG)     // 96 KB

__global__ __launch_bounds__(256, 2)
void gemm_hmma(Batch p, int M, int N, int K)
{
    extern __shared__ __align__(1024) char smem[];
    const int z = blockIdx.z;
    const __nv_bfloat16* __restrict__ Ah = p.Ah[z];
    const __nv_bfloat16* __restrict__ Al = p.Al[z];
    const __nv_bfloat16* __restrict__ Bh = p.Bh[z];
    const __nv_bfloat16* __restrict__ Bl = p.Bl[z];

    const int tid = threadIdx.x;
    const int wid = tid >> 5, lid = tid & 31;
    const int wm = wid & 3, wn = wid >> 2;       // 4(m) x 2(n)
    const int m0 = blockIdx.y * 128, n0 = blockIdx.x * 64;
    const uint32_t sb = smem_u32(smem);

    float c[2][4][4];
#pragma unroll
    for (int i = 0; i < 2; i++)
#pragma unroll
        for (int j = 0; j < 4; j++)
#pragma unroll
            for (int q = 0; q < 4; q++) c[i][j][q] = 0.f;

    const int NC = K >> 6;

    // A: 128 rows x 8 16B-chunks (x2 hi/lo); B: 64 rows x 8 chunks (x2)
#define LOAD_STAGE(cchunk) do { \
        const uint32_t st_ = sb + ((cchunk) & 1) * STG; \
        const int k0_ = (cchunk) << 6; \
        _Pragma("unroll") \
        for (int i_ = 0; i_ < 4; i_++) { \
            int idx_ = i_ * 256 + tid; \
            int r_ = idx_ >> 3, u_ = idx_ & 7; \
            uint32_t sw_ = SWZ((uint32_t)(r_ * 128 + u_ * 16)); \
            int gm_ = m0 + r_; \
            if (gm_ < M) { \
                CP_ASYNC16(st_ + T_AH + sw_, (const char*)(Ah + (size_t)gm_ * K + k0_) + u_ * 16); \
                CP_ASYNC16(st_ + T_AL + sw_, (const char*)(Al + (size_t)gm_ * K + k0_) + u_ * 16); \
            } else { \
                STS_ZERO16(st_ + T_AH + sw_); \
                STS_ZERO16(st_ + T_AL + sw_); \
            } \
        } \
        _Pragma("unroll") \
        for (int i_ = 0; i_ < 2; i_++) { \
            int idx_ = i_ * 256 + tid; \
            int r_ = idx_ >> 3, u_ = idx_ & 7; \
            uint32_t sw_ = SWZ((uint32_t)(r_ * 128 + u_ * 16)); \
            int gn_ = n0 + r_; \
            CP_ASYNC16(st_ + T_BH + sw_, (const char*)(Bh + (size_t)gn_ * K + k0_) + u_ * 16); \
            CP_ASYNC16(st_ + T_BL + sw_, (const char*)(Bl + (size_t)gn_ * K + k0_) + u_ * 16); \
        } \
        CP_COMMIT(); \
    } while (0)

    LOAD_STAGE(0);

    const int q8 = lid >> 3, lr = lid & 7;

    for (int cc = 0; cc < NC; cc++) {
        __syncthreads();
        if (cc + 1 < NC) { LOAD_STAGE(cc + 1); } else { CP_COMMIT(); }
        CP_WAIT1();
        __syncthreads();

        const uint32_t st = sb + (cc & 1) * STG;
#pragma unroll
        for (int ks = 0; ks < 4; ks++) {
            const int kb = ks * 32;
            uint32_t ah[2][4], al[2][4], bh[4][2], bl[4][2];
#pragma unroll
            for (int mi = 0; mi < 2; mi++) {
                uint32_t off = SWZ((uint32_t)(
                    (wm * 32 + mi * 16 + lr + (q8 & 1) * 8) * 128 + kb + (q8 >> 1) * 16));
                ldsm4(ah[mi], st + T_AH + off);
                ldsm4(al[mi], st + T_AL + off);
            }
#pragma unroll
            for (int njp = 0; njp < 2; njp++) {
                uint32_t off = SWZ((uint32_t)(
                    (wn * 32 + njp * 16 + lr + (q8 >> 1) * 8) * 128 + kb + (q8 & 1) * 16));
                uint32_t t0[4], t1[4];
                ldsm4(t0, st + T_BH + off);
                ldsm4(t1, st + T_BL + off);
                bh[2 * njp][0] = t0[0]; bh[2 * njp][1] = t0[1];
                bh[2 * njp + 1][0] = t0[2]; bh[2 * njp + 1][1] = t0[3];
                bl[2 * njp][0] = t1[0]; bl[2 * njp][1] = t1[1];
                bl[2 * njp + 1][0] = t1[2]; bl[2 * njp + 1][1] = t1[3];
            }
#pragma unroll
            for (int mi = 0; mi < 2; mi++)
#pragma unroll
                for (int nj = 0; nj < 4; nj++) {
                    mma16816(c[mi][nj], ah[mi], bh[nj][0], bh[nj][1]);
                    mma16816(c[mi][nj], ah[mi], bl[nj][0], bl[nj][1]);
                    mma16816(c[mi][nj], al[mi], bh[nj][0], bh[nj][1]);
                }
        }
    }

    const int lr4 = lid >> 2, lc = (lid & 3) * 2;
    const float* __restrict__ bias = p.bias[z];
#pragma unroll
    for (int mi = 0; mi < 2; mi++) {
        int row = m0 + wm * 32 + mi * 16 + lr4;
#pragma unroll
        for (int nj = 0; nj < 4; nj++) {
            int col = n0 + wn * 32 + nj * 8 + lc;
            float2 b2 = *(const float2*)(bias + col);
            float v00 = c[mi][nj][0] + b2.x, v01 = c[mi][nj][1] + b2.y;
            float v10 = c[mi][nj][2] + b2.x, v11 = c[mi][nj][3] + b2.y;
            if (p.obf) {
                __nv_bfloat16* Ch = p.Ch[z];
                __nv_bfloat16* Cl = p.Cl[z];
                uint32_t h0, l0, h1, l1;
                pack_split(v00, v01, h0, l0);
                pack_split(v10, v11, h1, l1);
                if (row < M) {
                    *(uint32_t*)(Ch + (size_t)row * N + col) = h0;
                    *(uint32_t*)(Cl + (size_t)row * N + col) = l0;
                }
                if (row + 8 < M) {
                    *(uint32_t*)(Ch + (size_t)(row + 8) * N + col) = h1;
                    *(uint32_t*)(Cl + (size_t)(row + 8) * N + col) = l1;
                }
            } else {
                float* C = p.C[z];
                if (row < M)
                    *(float2*)(C + (size_t)row * N + col) = make_float2(v00, v01);
                if (row + 8 < M)
                    *(float2*)(C + (size_t)(row + 8) * N + col) = make_float2(v10, v11);
            }
        }
    }
}

// ---------------------------------------------------------------------------
// HMMA flash attention, both streams fused, bf16 split-2 (3 terms).
// Block = 64 queries x 1 head, 4 warps, S chunks of 64. (unchanged from R4)
// ---------------------------------------------------------------------------
struct AttnParams {
    const __nv_bfloat16 *qh[2], *ql[2], *kh[2], *kl[2], *vh[2], *vl[2];
    const float *alpha, *beta;
    __nv_bfloat16 *oh, *ol;
};

#define ATT_STAGE 32768
#define A_KH 0
#define A_KL 8192
#define A_VH 16384
#define A_VL 24576
#define ATT_SMEM (2 * ATT_STAGE)
#define NCH 16
#define SOFTMAX_SCALE 0.125f

__global__ __launch_bounds__(128)
void attn_mma(AttnParams p)
{
    extern __shared__ __align__(1024) char smem[];
    const uint32_t sb = smem_u32(smem);
    const int tid = threadIdx.x;
    const int w = tid >> 5, lid = tid & 31;
    const int q8 = lid >> 3, lr = lid & 7;
    const int h = blockIdx.y;
    const int qbase = blockIdx.x * 64;
    const int colbase = h * EDIM;

    const float alpha = *p.alpha;
    const float beta  = *p.beta;

    float osave[8][4];

    for (int st = 0; st < 2; st++) {
        const __nv_bfloat16* __restrict__ qhp = p.qh[st];
        const __nv_bfloat16* __restrict__ qlp = p.ql[st];
        const __nv_bfloat16* __restrict__ khp = p.kh[st];
        const __nv_bfloat16* __restrict__ klp = p.kl[st];
        const __nv_bfloat16* __restrict__ vhp = p.vh[st];
        const __nv_bfloat16* __restrict__ vlp = p.vl[st];

#pragma unroll
        for (int i = 0; i < 4; i++) {
            int idx = i * 128 + tid;
            int r = idx >> 3, u = idx & 7;
            uint32_t sw = SWZ((uint32_t)(r * 128 + u * 16));
            CP_ASYNC16(sb + A_KH + sw,
                       (const char*)(qhp + (size_t)(qbase + r) * DINNER + colbase) + u * 16);
            CP_ASYNC16(sb + A_KL + sw,
                       (const char*)(qlp + (size_t)(qbase + r) * DINNER + colbase) + u * 16);
        }
        CP_COMMIT();
        CP_WAIT0();
        __syncthreads();

        uint32_t qfh[4][4], qfl[4][4];
#pragma unroll
        for (int ks = 0; ks < 4; ks++) {
            uint32_t off = SWZ((uint32_t)(
                (w * 16 + lr + (q8 & 1) * 8) * 128 + ks * 32 + (q8 >> 1) * 16));
            ldsm4(qfh[ks], sb + A_KH + off);
            ldsm4(qfl[ks], sb + A_KL + off);
        }
        __syncthreads();

        float o[8][4];
#pragma unroll
        for (int t = 0; t < 8; t++)
#pragma unroll
            for (int i = 0; i < 4; i++) o[t][i] = 0.f;
        float m0r = -INFINITY, m1r = -INFINITY;
        float l0 = 0.f, l1 = 0.f;

#define LOAD_KV(cchunk) do { \
            const uint32_t stg_ = sb + ((cchunk) & 1) * ATT_STAGE; \
            const int s0_ = (cchunk) * 64; \
            _Pragma("unroll") \
            for (int i_ = 0; i_ < 4; i_++) { \
                int idx_ = i_ * 128 + tid; \
                int r_ = idx_ >> 3, u_ = idx_ & 7; \
                uint32_t sw_ = SWZ((uint32_t)(r_ * 128 + u_ * 16)); \
                if (s0_ + r_ < SEQ_S) { \
                    const size_t go_ = (size_t)(s0_ + r_) * DINNER + colbase; \
                    CP_ASYNC16(stg_ + A_KH + sw_, (const char*)(khp + go_) + u_ * 16); \
                    CP_ASYNC16(stg_ + A_KL + sw_, (const char*)(klp + go_) + u_ * 16); \
                    CP_ASYNC16(stg_ + A_VH + sw_, (const char*)(vhp + go_) + u_ * 16); \
                    CP_ASYNC16(stg_ + A_VL + sw_, (const char*)(vlp + go_) + u_ * 16); \
                } else { \
                    STS_ZERO16(stg_ + A_KH + sw_); \
                    STS_ZERO16(stg_ + A_KL + sw_); \
                    STS_ZERO16(stg_ + A_VH + sw_); \
                    STS_ZERO16(stg_ + A_VL + sw_); \
                } \
            } \
            CP_COMMIT(); \
        } while (0)

        LOAD_KV(0);

        for (int cc = 0; cc < NCH; cc++) {
            __syncthreads();
            if (cc + 1 < NCH) { LOAD_KV(cc + 1); } else { CP_COMMIT(); }
            CP_WAIT1();
            __syncthreads();
            const uint32_t stg = sb + (cc & 1) * ATT_STAGE;

            float s[8][4];
#pragma unroll
            for (int t = 0; t < 8; t++)
#pragma unroll
                for (int i = 0; i < 4; i++) s[t][i] = 0.f;

#pragma unroll
            for (int ks = 0; ks < 4; ks++) {
                uint32_t bh[8][2], bl[8][2];
#pragma unroll
                for (int njp = 0; njp < 4; njp++) {
                    uint32_t off = SWZ((uint32_t)(
                        (njp * 16 + lr + (q8 >> 1) * 8) * 128 + ks * 32 + (q8 & 1) * 16));
                    uint32_t t0[4], t1[4];
                    ldsm4(t0, stg + A_KH + off);
                    ldsm4(t1, stg + A_KL + off);
                    bh[2 * njp][0] = t0[0]; bh[2 * njp][1] = t0[1];
                    bh[2 * njp + 1][0] = t0[2]; bh[2 * njp + 1][1] = t0[3];
                    bl[2 * njp][0] = t1[0]; bl[2 * njp][1] = t1[1];
                    bl[2 * njp + 1][0] = t1[2]; bl[2 * njp + 1][1] = t1[3];
                }
#pragma unroll
                for (int t = 0; t < 8; t++) {
                    mma16816(s[t], qfh[ks], bh[t][0], bh[t][1]);
                    mma16816(s[t], qfh[ks], bl[t][0], bl[t][1]);
                    mma16816(s[t], qfl[ks], bh[t][0], bh[t][1]);
                }
            }

            if (cc == NCH - 1) {
#pragma unroll
                for (int t = 5; t < 8; t++)
#pragma unroll
                    for (int i = 0; i < 4; i++) s[t][i] = -1e30f;
            }

            float ml0 = -1e30f, ml1 = -1e30f;
#pragma unroll
            for (int t = 0; t < 8; t++) {
                ml0 = fmaxf(ml0, fmaxf(s[t][0], s[t][1]));
                ml1 = fmaxf(ml1, fmaxf(s[t][2], s[t][3]));
            }
            ml0 = fmaxf(ml0, __shfl_xor_sync(0xffffffffu, ml0, 1));
            ml0 = fmaxf(ml0, __shfl_xor_sync(0xffffffffu, ml0, 2));
            ml1 = fmaxf(ml1, __shfl_xor_sync(0xffffffffu, ml1, 1));
            ml1 = fmaxf(ml1, __shfl_xor_sync(0xffffffffu, ml1, 2));

            float mn0 = fmaxf(m0r, ml0), mn1 = fmaxf(m1r, ml1);
            float c0 = __expf((m0r - mn0) * SOFTMAX_SCALE);
            float c1 = __expf((m1r - mn1) * SOFTMAX_SCALE);
            m0r = mn0; m1r = mn1;
            l0 *= c0; l1 *= c1;
#pragma unroll
            for (int t = 0; t < 8; t++) {
                o[t][0] *= c0; o[t][1] *= c0;
                o[t][2] *= c1; o[t][3] *= c1;
            }
#pragma unroll
            for (int t = 0; t < 8; t++) {
                float p0 = __expf((s[t][0] - mn0) * SOFTMAX_SCALE);
                float p1 = __expf((s[t][1] - mn0) * SOFTMAX_SCALE);
                float p2 = __expf((s[t][2] - mn1) * SOFTMAX_SCALE);
                float p3 = __expf((s[t][3] - mn1) * SOFTMAX_SCALE);
                l0 += p0 + p1; l1 += p2 + p3;
                s[t][0] = p0; s[t][1] = p1; s[t][2] = p2; s[t][3] = p3;
            }

#pragma unroll
            for (int ks = 0; ks < 4; ks++) {
                uint32_t pah[4], pal[4];
                pack_split(s[2 * ks][0],     s[2 * ks][1],     pah[0], pal[0]);
                pack_split(s[2 * ks][2],     s[2 * ks][3],     pah[1], pal[1]);
                pack_split(s[2 * ks + 1][0], s[2 * ks + 1][1], pah[2], pal[2]);
                pack_split(s[2 * ks + 1][2], s[2 * ks + 1][3], pah[3], pal[3]);
#pragma unroll
                for (int ep = 0; ep < 4; ep++) {
                    uint32_t off = SWZ((uint32_t)(
                        (ks * 16 + lr + (q8 & 1) * 8) * 128 + ep * 32 + (q8 >> 1) * 16));
                    uint32_t tv0[4], tv1[4];
                    ldsm4t(tv0, stg + A_VH + off);
                    ldsm4t(tv1, stg + A_VL + off);
                    mma16816(o[2 * ep],     pah, tv0[0], tv0[1]);
                    mma16816(o[2 * ep],     pah, tv1[0], tv1[1]);
                    mma16816(o[2 * ep],     pal, tv0[0], tv0[1]);
                    mma16816(o[2 * ep + 1], pah, tv0[2], tv0[3]);
                    mma16816(o[2 * ep + 1], pah, tv1[2], tv1[3]);
                    mma16816(o[2 * ep + 1], pal, tv0[2], tv0[3]);
                }
            }
        }

        l0 += __shfl_xor_sync(0xffffffffu, l0, 1);
        l0 += __shfl_xor_sync(0xffffffffu, l0, 2);
        l1 += __shfl_xor_sync(0xffffffffu, l1, 1);
        l1 += __shfl_xor_sync(0xffffffffu, l1, 2);
        float wgt = (st == 0) ? alpha : beta;
        float f0 = wgt / l0, f1 = wgt / l1;
        if (st == 0) {
#pragma unroll
            for (int t = 0; t < 8; t++) {
                osave[t][0] = o[t][0] * f0; osave[t][1] = o[t][1] * f0;
                osave[t][2] = o[t][2] * f1; osave[t][3] = o[t][3] * f1;
            }
        } else {
#pragma unroll
            for (int t = 0; t < 8; t++) {
                osave[t][0] += o[t][0] * f0; osave[t][1] += o[t][1] * f0;
                osave[t][2] += o[t][2] * f1; osave[t][3] += o[t][3] * f1;
            }
        }
        __syncthreads();
    }

    const int r0 = qbase + w * 16 + (lid >> 2);
#pragma unroll
    for (int t = 0; t < 8; t++) {
        int col = colbase + t * 8 + (lid & 3) * 2;
        uint32_t h0, lo0, h1, lo1;
        pack_split(osave[t][0], osave[t][1], h0, lo0);
        pack_split(osave[t][2], osave[t][3], h1, lo1);
        *(uint32_t*)(p.oh + (size_t)r0 * DINNER + col) = h0;
        *(uint32_t*)(p.ol + (size_t)r0 * DINNER + col) = lo0;
        *(uint32_t*)(p.oh + (size_t)(r0 + 8) * DINNER + col) = h1;
        *(uint32_t*)(p.ol + (size_t)(r0 + 8) * DINNER + col) = lo1;
    }
}

// ---------------------------------------------------------------------------
// Launch
// ---------------------------------------------------------------------------
extern "C" void kernel_launch(void* const* d_in, const int* in_sizes, int n_in,
                              void* d_out, int out_size)
{
    const float* target = (const float*)d_in[0];
    const float* source = (const float*)d_in[1];
    const float* value  = (const float*)d_in[2];
    const float* Wq_s = (const float*)d_in[3];  const float* bq_s = (const float*)d_in[4];
    const float* Wk_s = (const float*)d_in[5];  const float* bk_s = (const float*)d_in[6];
    const float* Wv_s = (const float*)d_in[7];  const float* bv_s = (const float*)d_in[8];
    const float* Wq_l = (const float*)d_in[9];  const float* bq_l = (const float*)d_in[10];
    const float* Wk_l = (const float*)d_in[11]; const float* bk_l = (const float*)d_in[12];
    const float* Wv_l = (const float*)d_in[13]; const float* bv_l = (const float*)d_in[14];
    const float* Wo   = (const float*)d_in[15]; const float* bo   = (const float*)d_in[16];
    const float* alpha = (const float*)d_in[17];
    const float* beta  = (const float*)d_in[18];
    float* out = (float*)d_out;

    __nv_bfloat16 *th, *tl, *sh, *sl, *vh, *vl2, *ah, *al;
    cudaGetSymbolAddress((void**)&th,  g_th);  cudaGetSymbolAddress((void**)&tl,  g_tl);
    cudaGetSymbolAddress((void**)&sh,  g_sh);  cudaGetSymbolAddress((void**)&sl,  g_sl);
    cudaGetSymbolAddress((void**)&vh,  g_vh);  cudaGetSymbolAddress((void**)&vl2, g_vl2);
    cudaGetSymbolAddress((void**)&ah,  g_ah);  cudaGetSymbolAddress((void**)&al,  g_al);

    __nv_bfloat16 *qsh, *qsl, *qlh, *qll, *ksh, *ksl, *vsh, *vsl, *klh, *kll, *vlh, *vll;
    cudaGetSymbolAddress((void**)&qsh, g_qsh); cudaGetSymbolAddress((void**)&qsl, g_qsl);
    cudaGetSymbolAddress((void**)&qlh, g_qlh); cudaGetSymbolAddress((void**)&qll, g_qll);
    cudaGetSymbolAddress((void**)&ksh, g_ksh); cudaGetSymbolAddress((void**)&ksl, g_ksl);
    cudaGetSymbolAddress((void**)&vsh, g_vsh); cudaGetSymbolAddress((void**)&vsl, g_vsl);
    cudaGetSymbolAddress((void**)&klh, g_klh); cudaGetSymbolAddress((void**)&kll, g_kll);
    cudaGetSymbolAddress((void**)&vlh, g_vlh); cudaGetSymbolAddress((void**)&vll, g_vll);

    __nv_bfloat16 *wqsh, *wqsl, *wqlh, *wqll, *wksh, *wksl, *wvsh, *wvsl;
    __nv_bfloat16 *wklh, *wkll, *wvlh, *wvll, *woh, *wol;
    cudaGetSymbolAddress((void**)&wqsh, g_wqsh); cudaGetSymbolAddress((void**)&wqsl, g_wqsl);
    cudaGetSymbolAddress((void**)&wqlh, g_wqlh); cudaGetSymbolAddress((void**)&wqll, g_wqll);
    cudaGetSymbolAddress((void**)&wksh, g_wksh); cudaGetSymbolAddress((void**)&wksl, g_wksl);
    cudaGetSymbolAddress((void**)&wvsh, g_wvsh); cudaGetSymbolAddress((void**)&wvsl, g_wvsl);
    cudaGetSymbolAddress((void**)&wklh, g_wklh); cudaGetSymbolAddress((void**)&wkll, g_wkll);
    cudaGetSymbolAddress((void**)&wvlh, g_wvlh); cudaGetSymbolAddress((void**)&wvll, g_wvll);
    cudaGetSymbolAddress((void**)&woh,  g_woh);  cudaGetSymbolAddress((void**)&wol,  g_wol);

    cudaFuncSetAttribute(gemm_hmma, cudaFuncAttributeMaxDynamicSharedMemorySize, GEMM_SMEM);
    cudaFuncSetAttribute(attn_mma, cudaFuncAttributeMaxDynamicSharedMemorySize, ATT_SMEM);

    // --- prepass ---
    split_f32<<<2048, 256>>>(target, th, tl, BL * DMODEL);
    split_f32<<<1024, 256>>>(source, sh, sl, SEQ_S * DLLM);
    split_f32<<<1024, 256>>>(value,  vh, vl2, SEQ_S * DLLM);
    dim3 tb(32, 8);
    split_transpose<<<dim3(DINNER / 32, DMODEL / 32), tb>>>(Wq_s, wqsh, wqsl, DMODEL, DINNER);
    split_transpose<<<dim3(DINNER / 32, DMODEL / 32), tb>>>(Wq_l, wqlh, wqll, DMODEL, DINNER);
    split_transpose<<<dim3(DINNER / 32, DLLM / 32),   tb>>>(Wk_s, wksh, wksl, DLLM, DINNER);
    split_transpose<<<dim3(DINNER / 32, DLLM / 32),   tb>>>(Wv_s, wvsh, wvsl, DLLM, DINNER);
    split_transpose<<<dim3(DINNER / 32, DLLM / 32),   tb>>>(Wk_l, wklh, wkll, DLLM, DINNER);
    split_transpose<<<dim3(DINNER / 32, DLLM / 32),   tb>>>(Wv_l, wvlh, wvll, DLLM, DINNER);
    split_transpose<<<dim3(DLLM / 32, DINNER / 32),   tb>>>(Wo,   woh,  wol,  DINNER, DLLM);

    // --- Q projections -> bf16 split ---
    {
        Batch p = {};
        p.obf = 1;
        p.Ah[0] = th; p.Al[0] = tl; p.Bh[0] = wqsh; p.Bl[0] = wqsl; p.bias[0] = bq_s;
        p.Ch[0] = qsh; p.Cl[0] = qsl;
        p.Ah[1] = th; p.Al[1] = tl; p.Bh[1] = wqlh; p.Bl[1] = wqll; p.bias[1] = bq_l;
        p.Ch[1] = qlh; p.Cl[1] = qll;
        dim3 g(DINNER / 64, BL / 128, 2);            // (16, 64, 2)
        gemm_hmma<<<g, 256, GEMM_SMEM>>>(p, BL, DINNER, DMODEL);
    }
    // --- KV projections -> bf16 split ---
    {
        Batch p = {};
        p.obf = 1;
        p.Ah[0] = sh; p.Al[0] = sl;  p.Bh[0] = wksh; p.Bl[0] = wksl; p.bias[0] = bk_s;
        p.Ch[0] = ksh; p.Cl[0] = ksl;
        p.Ah[1] = vh; p.Al[1] = vl2; p.Bh[1] = wvsh; p.Bl[1] = wvsl; p.bias[1] = bv_s;
        p.Ch[1] = vsh; p.Cl[1] = vsl;
        p.Ah[2] = sh; p.Al[2] = sl;  p.Bh[2] = wklh; p.Bl[2] = wkll; p.bias[2] = bk_l;
        p.Ch[2] = klh; p.Cl[2] = kll;
        p.Ah[3] = vh; p.Al[3] = vl2; p.Bh[3] = wvlh; p.Bl[3] = wvll; p.bias[3] = bv_l;
        p.Ch[3] = vlh; p.Cl[3] = vll;
        dim3 g(DINNER / 64, (SEQ_S + 127) / 128, 4); // (16, 8, 4)
        gemm_hmma<<<g, 256, GEMM_SMEM>>>(p, SEQ_S, DINNER, DLLM);
    }

    // --- fused dual-stream flash attention (HMMA) ---
    {
        AttnParams ap = {};
        ap.qh[0] = qsh; ap.ql[0] = qsl; ap.kh[0] = ksh; ap.kl[0] = ksl;
        ap.vh[0] = vsh; ap.vl[0] = vsl;
        ap.qh[1] = qlh; ap.ql[1] = qll; ap.kh[1] = klh; ap.kl[1] = kll;
        ap.vh[1] = vlh; ap.vl[1] = vll;
        ap.alpha = alpha; ap.beta = beta;
        ap.oh = ah; ap.ol = al;
        dim3 g(BL / 64, NHEAD);
        attn_mma<<<g, 128, ATT_SMEM>>>(ap);
    }

    // --- final projection (fp32 out) ---
    {
        Batch p = {};
        p.obf = 0;
        p.Ah[0] = ah; p.Al[0] = al; p.Bh[0] = woh; p.Bl[0] = wol; p.bias[0] = bo;
        p.C[0] = out;
        dim3 g(DLLM / 64, BL / 128, 1);              // (64, 64, 1)
        gemm_hmma<<<g, 256, GEMM_SMEM>>>(p, BL, DLLM, DINNER);
    }
}